// round 15
// baseline (speedup 1.0000x reference)
#include <cuda_runtime.h>
#include <cuda_bf16.h>
#include <cstdint>

#define B_    16
#define L_    512
#define H_    256
#define V_    32000
#define HALF_ 128
#define TOK   (B_*L_)   // 8192
#define H2_   (2*H_)    // 512
#define NGRP  64        // 8-step groups per pair (63 full + tail singles)

typedef __nv_bfloat16 bf16;
typedef unsigned long long ull;

// ---------------- scratch (device globals) ----------------
__device__ __align__(16) bf16  g_hh [TOK*H_];
__device__ __align__(16) bf16  g_hl [TOK*H_];
__device__ __align__(16) bf16  g_W1h[H2_*H_], g_W1l[H2_*H_];
__device__ __align__(16) bf16  g_W2h[H_*H2_], g_W2l[H_*H2_];
__device__ __align__(16) bf16  g_Wkh[H_*H_],  g_Wkl[H_*H_];
__device__ __align__(16) bf16  g_hidh[TOK*H2_], g_hidl[TOK*H2_];
__device__ __align__(16) float g_x  [TOK*H_];
__device__ __align__(16) bf16  g_hnh[TOK*H_], g_hnl[TOK*H_];
__device__ __align__(16) float g_kraw[TOK*H_];        // [ks | ke] per token, stride 256
__device__ __align__(16) float g_kns[B_*512*HALF_];   // padded to 512 timesteps
__device__ __align__(16) float g_kne[B_*512*HALF_];
__device__ __align__(16) float g_gram[B_*2*NGRP*32];  // 28 coeffs (+pad) per 8-step group
__device__ __align__(16) float g_c  [B_*H_];
__device__ __align__(16) float g_r  [B_*H_];

// ---------------- helpers ----------------
__device__ __forceinline__ void gdc_wait() {
    asm volatile("griddepcontrol.wait;" ::: "memory");
}
__device__ __forceinline__ void split2(float v, bf16& hi, bf16& lo) {
    hi = __float2bfloat16(v);
    lo = __float2bfloat16(v - __bfloat162float(hi));
}
__device__ __forceinline__ uint32_t s2u(const void* p) {
    return (uint32_t)__cvta_generic_to_shared(p);
}
__device__ __forceinline__ void cp16(void* s, const void* g) {
    asm volatile("cp.async.cg.shared.global [%0], [%1], 16;\n" :: "r"(s2u(s)), "l"(g));
}
// packed f32x2
__device__ __forceinline__ ull pk2(float a, float b) {
    ull r; asm("mov.b64 %0, {%1, %2};" : "=l"(r) : "f"(a), "f"(b)); return r;
}
__device__ __forceinline__ float2 upk2(ull v) {
    float2 f; asm("mov.b64 {%0, %1}, %2;" : "=f"(f.x), "=f"(f.y) : "l"(v)); return f;
}
__device__ __forceinline__ ull ffma2(ull a, ull b, ull c) {
    ull d; asm("fma.rn.f32x2 %0, %1, %2, %3;" : "=l"(d) : "l"(a), "l"(b), "l"(c)); return d;
}
__device__ __forceinline__ ull fmul2(ull a, ull b) {
    ull d; asm("mul.rn.f32x2 %0, %1, %2;" : "=l"(d) : "l"(a), "l"(b)); return d;
}

// ---------------- merged prep: weight splits + embedding gather ----------------
__global__ void prep_kernel(const int* __restrict__ seq, const float* __restrict__ embed,
                            const float* __restrict__ W1, const float* __restrict__ W2,
                            const float* __restrict__ Wsem, const float* __restrict__ Wepi,
                            bf16* __restrict__ W1h, bf16* __restrict__ W1l,
                            bf16* __restrict__ W2h, bf16* __restrict__ W2l,
                            bf16* __restrict__ Wkh, bf16* __restrict__ Wkl,
                            bf16* __restrict__ hh, bf16* __restrict__ hl) {
    gdc_wait();
    int bx = blockIdx.x, tid = threadIdx.x;
    if (bx < 1280) {
        int i = bx * 256 + tid;
        const float* src; bf16 *hi, *lo; int off;
        if (i < 131072)      { src = W1;   hi = W1h; lo = W1l; off = i; }
        else if (i < 262144) { src = W2;   hi = W2h; lo = W2l; off = i - 131072; }
        else if (i < 294912) { src = Wsem; hi = Wkh; lo = Wkl; off = i - 262144; }
        else                 { src = Wepi; hi = Wkh + 32768; lo = Wkl + 32768; off = i - 294912; }
        bf16 a, b; split2(src[off], a, b);
        hi[off] = a; lo[off] = b;
    } else {
        int tok = (bx - 1280) * 4 + (tid >> 6);
        int col = (tid & 63) * 4;
        int s = __ldg(seq + tok);
        float4 v = *(const float4*)&embed[(size_t)s * H_ + col];
        bf16 h4[4], l4[4];
        split2(v.x, h4[0], l4[0]); split2(v.y, h4[1], l4[1]);
        split2(v.z, h4[2], l4[2]); split2(v.w, h4[3], l4[3]);
        *(uint2*)&hh[(size_t)tok * H_ + col] = *(uint2*)h4;
        *(uint2*)&hl[(size_t)tok * H_ + col] = *(uint2*)l4;
    }
}

// ---------------- bf16x3 split-GEMM, 128x64 tiles, term-major MMA order ----------------
#define GBM 128
#define GBN 64
#define GBK 32
#define SLD (GBK + 8)
#define ATILE (GBM * SLD)
#define BTILE (GBN * SLD)
#define GSMEM ((4*ATILE + 4*BTILE) * 2)   // 61440

#define MMA_BF16(d, a, b) asm volatile( \
    "mma.sync.aligned.m16n8k16.row.col.f32.bf16.bf16.f32 " \
    "{%0,%1,%2,%3},{%4,%5,%6,%7},{%8,%9},{%0,%1,%2,%3};" \
    : "+f"(d[0]), "+f"(d[1]), "+f"(d[2]), "+f"(d[3]) \
    : "r"(a[0]), "r"(a[1]), "r"(a[2]), "r"(a[3]), "r"(b[0]), "r"(b[1]))

#define LDSM4(r0, r1, r2, r3, addr) asm volatile( \
    "ldmatrix.sync.aligned.m8n8.x4.shared.b16 {%0,%1,%2,%3}, [%4];" \
    : "=r"(r0), "=r"(r1), "=r"(r2), "=r"(r3) : "r"(addr))

template<int EPI>
__global__ __launch_bounds__(256, 2)
void gemm3_kernel(const bf16* __restrict__ Ah, const bf16* __restrict__ Al,
                  const bf16* __restrict__ Bh, const bf16* __restrict__ Bl,
                  const float* __restrict__ bias, const bf16* __restrict__ Rh,
                  const bf16* __restrict__ Rl,
                  float* __restrict__ Cf, bf16* __restrict__ Ch, bf16* __restrict__ Cl,
                  int M, int N, int K) {
    extern __shared__ bf16 smem[];
    bf16* As_h = smem;
    bf16* As_l = smem + 2*ATILE;
    bf16* Bs_h = smem + 4*ATILE;
    bf16* Bs_l = smem + 4*ATILE + 2*BTILE;

    const int tid  = threadIdx.x;
    const int wid  = tid >> 5;
    const int lane = tid & 31;
    const int wm   = (wid & 3) * 32;
    const int wn   = (wid >> 2) * 32;
    const int r    = lane >> 2;
    const int q    = lane & 3;
    const int m0   = blockIdx.y * GBM;
    const int n0   = blockIdx.x * GBN;

    const int aoff = (wm + (lane & 15)) * SLD + ((lane >> 4) * 8);
    const int boff = (wn + ((lane >> 4) * 8) + (lane & 7)) * SLD + (((lane >> 3) & 1) * 8);

    float c[2][4][4];
#pragma unroll
    for (int mt = 0; mt < 2; mt++)
#pragma unroll
        for (int nt = 0; nt < 4; nt++)
#pragma unroll
            for (int e = 0; e < 4; e++) c[mt][nt][e] = 0.f;

    auto load_stage = [&](int st, int k0) {
#pragma unroll
        for (int i = tid; i < 512; i += 256) {
            int row = i >> 2, kc = (i & 3) * 8;
            size_t ga = (size_t)(m0 + row) * K + k0 + kc;
            int so = st * ATILE + row * SLD + kc;
            cp16(As_h + so, Ah + ga);
            cp16(As_l + so, Al + ga);
        }
        {
            int i = tid;
            int row = i >> 2, kc = (i & 3) * 8;
            size_t gb = (size_t)(n0 + row) * K + k0 + kc;
            int so = st * BTILE + row * SLD + kc;
            cp16(Bs_h + so, Bh + gb);
            cp16(Bs_l + so, Bl + gb);
        }
        asm volatile("cp.async.commit_group;\n");
    };

    gdc_wait();
    const int T = K / GBK;
    load_stage(0, 0);

    for (int t = 0; t < T; t++) {
        if (t + 1 < T) {
            load_stage((t + 1) & 1, (t + 1) * GBK);
            asm volatile("cp.async.wait_group 1;\n");
        } else {
            asm volatile("cp.async.wait_group 0;\n");
        }
        __syncthreads();

        const uint32_t aBh = s2u(As_h + (t & 1) * ATILE + aoff);
        const uint32_t aBl = s2u(As_l + (t & 1) * ATILE + aoff);
        const uint32_t bBh = s2u(Bs_h + (t & 1) * BTILE + boff);
        const uint32_t bBl = s2u(Bs_l + (t & 1) * BTILE + boff);

#pragma unroll
        for (int kk = 0; kk < GBK; kk += 16) {
            const uint32_t ko = kk * 2;
            uint32_t Afh[2][4], Afl[2][4], Bfh[4][2], Bfl[4][2];
#pragma unroll
            for (int mt = 0; mt < 2; mt++) {
                LDSM4(Afh[mt][0], Afh[mt][1], Afh[mt][2], Afh[mt][3],
                      aBh + (uint32_t)(mt * 16 * SLD * 2) + ko);
                LDSM4(Afl[mt][0], Afl[mt][1], Afl[mt][2], Afl[mt][3],
                      aBl + (uint32_t)(mt * 16 * SLD * 2) + ko);
            }
#pragma unroll
            for (int ntp = 0; ntp < 2; ntp++) {
                LDSM4(Bfh[2*ntp][0], Bfh[2*ntp][1], Bfh[2*ntp+1][0], Bfh[2*ntp+1][1],
                      bBh + (uint32_t)(ntp * 16 * SLD * 2) + ko);
                LDSM4(Bfl[2*ntp][0], Bfl[2*ntp][1], Bfl[2*ntp+1][0], Bfl[2*ntp+1][1],
                      bBl + (uint32_t)(ntp * 16 * SLD * 2) + ko);
            }
#pragma unroll
            for (int mt = 0; mt < 2; mt++)
#pragma unroll
                for (int nt = 0; nt < 4; nt++)
                    MMA_BF16(c[mt][nt], Afh[mt], Bfh[nt]);
#pragma unroll
            for (int mt = 0; mt < 2; mt++)
#pragma unroll
                for (int nt = 0; nt < 4; nt++)
                    MMA_BF16(c[mt][nt], Afh[mt], Bfl[nt]);
#pragma unroll
            for (int mt = 0; mt < 2; mt++)
#pragma unroll
                for (int nt = 0; nt < 4; nt++)
                    MMA_BF16(c[mt][nt], Afl[mt], Bfh[nt]);
        }
        __syncthreads();
    }

#pragma unroll
    for (int mt = 0; mt < 2; mt++)
#pragma unroll
        for (int nt = 0; nt < 4; nt++) {
            int gm = m0 + wm + mt*16 + r;
            int gn = n0 + wn + nt*8 + q*2;
#pragma unroll
            for (int half = 0; half < 2; half++) {
                int m = gm + half*8;
                float v0 = c[mt][nt][half*2 + 0];
                float v1 = c[mt][nt][half*2 + 1];
                size_t o = (size_t)m * N + gn;
                if (EPI == 1) {
                    v0 = fmaxf(v0 + bias[gn],     0.f);
                    v1 = fmaxf(v1 + bias[gn + 1], 0.f);
                    bf16 h0, l0, h1, l1;
                    split2(v0, h0, l0); split2(v1, h1, l1);
                    __nv_bfloat162 ph; ph.x = h0; ph.y = h1;
                    __nv_bfloat162 pl; pl.x = l0; pl.y = l1;
                    *(__nv_bfloat162*)&Ch[o] = ph;
                    *(__nv_bfloat162*)&Cl[o] = pl;
                } else if (EPI == 2) {
                    __nv_bfloat162 rh = *(const __nv_bfloat162*)&Rh[o];
                    __nv_bfloat162 rl = *(const __nv_bfloat162*)&Rl[o];
                    v0 += bias[gn]     + __bfloat162float(rh.x) + __bfloat162float(rl.x);
                    v1 += bias[gn + 1] + __bfloat162float(rh.y) + __bfloat162float(rl.y);
                    float2 p; p.x = v0; p.y = v1;
                    *(float2*)&Cf[o] = p;
                } else {
                    float2 p; p.x = v0; p.y = v1;
                    *(float2*)&Cf[o] = p;
                }
            }
        }
}

// ---------------- LayerNorm: one warp per TWO rows ----------------
__global__ void ln_kernel(const float* __restrict__ x, bf16* __restrict__ hh,
                          bf16* __restrict__ hl, const float* __restrict__ gamma,
                          const float* __restrict__ beta) {
    gdc_wait();
    int row0 = (blockIdx.x * 8 + (threadIdx.x >> 5)) * 2;
    int lane = threadIdx.x & 31;
    const float* xr0 = x + (size_t)row0 * H_ + lane * 8;
    const float* xr1 = xr0 + H_;
    float4 a0 = *(const float4*)xr0;
    float4 a1 = *(const float4*)(xr0 + 4);
    float4 b0v = *(const float4*)xr1;
    float4 b1v = *(const float4*)(xr1 + 4);
    float s0  = a0.x+a0.y+a0.z+a0.w+a1.x+a1.y+a1.z+a1.w;
    float q0  = a0.x*a0.x+a0.y*a0.y+a0.z*a0.z+a0.w*a0.w
              + a1.x*a1.x+a1.y*a1.y+a1.z*a1.z+a1.w*a1.w;
    float s1  = b0v.x+b0v.y+b0v.z+b0v.w+b1v.x+b1v.y+b1v.z+b1v.w;
    float q1  = b0v.x*b0v.x+b0v.y*b0v.y+b0v.z*b0v.z+b0v.w*b0v.w
              + b1v.x*b1v.x+b1v.y*b1v.y+b1v.z*b1v.z+b1v.w*b1v.w;
#pragma unroll
    for (int o = 16; o; o >>= 1) {
        s0 += __shfl_xor_sync(0xffffffffu, s0, o);
        q0 += __shfl_xor_sync(0xffffffffu, q0, o);
        s1 += __shfl_xor_sync(0xffffffffu, s1, o);
        q1 += __shfl_xor_sync(0xffffffffu, q1, o);
    }
    float4 g0 = *(const float4*)(gamma + lane*8);
    float4 g1 = *(const float4*)(gamma + lane*8 + 4);
    float4 c0 = *(const float4*)(beta  + lane*8);
    float4 c1 = *(const float4*)(beta  + lane*8 + 4);
#pragma unroll
    for (int rr = 0; rr < 2; rr++) {
        float sm = rr ? s1 : s0, sq = rr ? q1 : q0;
        float4 v0 = rr ? b0v : a0, v1 = rr ? b1v : a1;
        float mu  = sm * (1.0f / H_);
        float var = sq * (1.0f / H_) - mu * mu;
        float inv = rsqrtf(var + 1e-5f);
        float y[8] = {
            (v0.x-mu)*inv*g0.x + c0.x, (v0.y-mu)*inv*g0.y + c0.y,
            (v0.z-mu)*inv*g0.z + c0.z, (v0.w-mu)*inv*g0.w + c0.w,
            (v1.x-mu)*inv*g1.x + c1.x, (v1.y-mu)*inv*g1.y + c1.y,
            (v1.z-mu)*inv*g1.z + c1.z, (v1.w-mu)*inv*g1.w + c1.w };
        bf16 oh[8], ol[8];
#pragma unroll
        for (int i = 0; i < 8; i++) split2(y[i], oh[i], ol[i]);
        *(uint4*)&hh[(size_t)(row0+rr) * H_ + lane*8] = *(uint4*)oh;
        *(uint4*)&hl[(size_t)(row0+rr) * H_ + lane*8] = *(uint4*)ol;
    }
}

// ---------------- fused key-normalize + 8-step Gram ----------------
// warp per 8-step group: normalize 8 keys, write kns, compute 28 pairwise dots.
__global__ void knorm_gram_kernel(const float* __restrict__ kraw, float* __restrict__ kns,
                                  float* __restrict__ kne, float* __restrict__ gram) {
    gdc_wait();
    int w = blockIdx.x * 8 + (threadIdx.x >> 5);   // 0..2047
    int lane = threadIdx.x & 31;
    int grp = w & (NGRP - 1);     // 0..63
    int pr  = w >> 6;             // pair 0..31
    int mm = pr & 1, b = pr >> 1;

    float4 n[8];
    float ss[8];
#pragma unroll
    for (int i = 0; i < 8; i++) {
        int t = grp*8 + i;
        if (t < 511) n[i] = *(const float4*)(kraw + ((size_t)(b*L_ + t))*H_ + mm*HALF_ + lane*4);
        else         n[i] = make_float4(0.f, 0.f, 0.f, 0.f);
        ss[i] = n[i].x*n[i].x + n[i].y*n[i].y + n[i].z*n[i].z + n[i].w*n[i].w;
    }
#pragma unroll
    for (int o = 16; o; o >>= 1)
#pragma unroll
        for (int i = 0; i < 8; i++) ss[i] += __shfl_xor_sync(0xffffffffu, ss[i], o);

    float* dstb = (mm ? kne : kns) + (size_t)b*512*HALF_;
#pragma unroll
    for (int i = 0; i < 8; i++) {
        float inv = 1.0f / fmaxf(sqrtf(ss[i]), 1e-12f);
        n[i].x *= inv; n[i].y *= inv; n[i].z *= inv; n[i].w *= inv;
        int t = grp*8 + i;
        if (t < 511) *(float4*)(dstb + (size_t)t*HALF_ + lane*4) = n[i];
    }
    if (grp >= NGRP - 1) return;   // group 63 tail handled as singles in scan

    float gg[28];
    int idx = 0;
#pragma unroll
    for (int i = 1; i < 8; i++)
#pragma unroll
        for (int j = 0; j < i; j++)
            gg[idx++] = n[j].x*n[i].x + n[j].y*n[i].y + n[j].z*n[i].z + n[j].w*n[i].w;
#pragma unroll
    for (int o = 16; o; o >>= 1)
#pragma unroll
        for (int e = 0; e < 28; e++) gg[e] += __shfl_xor_sync(0xffffffffu, gg[e], o);

    if (lane == 0) {
        float* gp = gram + (size_t)(pr*NGRP + grp) * 32;
#pragma unroll
        for (int e = 0; e < 7; e++)
            *(float4*)(gp + e*4) = *(float4*)&gg[e*4];
    }
}

// ---------------- 8-step blocked delta-rule scan: SMEM-staged, 2 rows/warp ----------------
__global__ __launch_bounds__(256, 2)
void scan_kernel(const float* __restrict__ kraw,
                 const float* __restrict__ kns, const float* __restrict__ kne,
                 const float* __restrict__ gram, float* __restrict__ co) {
    __shared__ float ksm[2][32*HALF_];   // 2 x 16KB

    const int bx = blockIdx.x;
    const int rg = bx & 7;
    const int pr = bx >> 3;              // pair 0..31
    const int mm = pr & 1, b = pr >> 1;
    const int w = threadIdx.x >> 5, lane = threadIdx.x & 31;
    const int r0 = rg*16 + w*2;          // rows r0, r0+1

    const float* kn = (mm ? kne : kns) + (size_t)b*512*HALF_;
    const float* kr = kraw + (size_t)b*L_*H_ + mm*HALF_;
    const float* gr = gram + (size_t)pr*NGRP*32;

    auto issue = [&](int cc) {
        const float* src = kn + (size_t)cc*32*HALF_;
        float* dst = ksm[cc & 1];
#pragma unroll
        for (int j = 0; j < 4; j++) {
            int pos = threadIdx.x + j*256;
            cp16(dst + pos*4, src + pos*4);
        }
        asm volatile("cp.async.commit_group;\n");
    };

    ull s0a = 0, s0b = 0, s1a = 0, s1b = 0;

    gdc_wait();
    issue(0); issue(1);

    for (int c = 0; c < 16; c++) {
        if (c == 15) asm volatile("cp.async.wait_group 0;\n");
        else         asm volatile("cp.async.wait_group 1;\n");
        __syncthreads();
        const float* buf = ksm[c & 1];
        const int ngrp = (c == 15) ? 3 : 4;      // chunk 15: groups 60..62, then singles
        for (int j = 0; j < ngrp; j++) {
            const int grp = c*4 + j;
            const float* nrows = buf + (j*8)*HALF_ + lane*4;

            // dots v[i] = s0.n_i, v[8+i] = s1.n_i
            float v[16];
#pragma unroll
            for (int i = 0; i < 8; i++) {
                float4 n4 = *(const float4*)(nrows + i*HALF_);
                ull na = pk2(n4.x, n4.y), nb = pk2(n4.z, n4.w);
                float2 ta = upk2(ffma2(s0b, nb, fmul2(s0a, na)));
                v[i]   = ta.x + ta.y;
                float2 tb = upk2(ffma2(s1b, nb, fmul2(s1a, na)));
                v[8+i] = tb.x + tb.y;
            }
            // gram coeffs + raw keys (issue early)
            float gg[28];
#pragma unroll
            for (int e = 0; e < 7; e++)
                *(float4*)&gg[e*4] = *(const float4*)(gr + grp*32 + e*4);
            float2 kk[8];
            const float* kb = kr + (size_t)(grp*8)*H_ + r0;
#pragma unroll
            for (int i = 0; i < 8; i++)
                kk[i] = *(const float2*)(kb + (size_t)i*H_);

            // transposed butterfly: 16 values -> lane r*16 + i*2
            float u[8];
#pragma unroll
            for (int jj = 0; jj < 8; jj++) {
                float lo = v[jj], hi = v[jj+8];
                float mine = (lane & 16) ? hi : lo;
                float oth  = (lane & 16) ? lo : hi;
                u[jj] = mine + __shfl_xor_sync(0xffffffffu, oth, 16);
            }
            float w2[4];
#pragma unroll
            for (int jj = 0; jj < 4; jj++) {
                float mine = (lane & 8) ? u[jj+4] : u[jj];
                float oth  = (lane & 8) ? u[jj]   : u[jj+4];
                w2[jj] = mine + __shfl_xor_sync(0xffffffffu, oth, 8);
            }
            float x2[2];
#pragma unroll
            for (int jj = 0; jj < 2; jj++) {
                float mine = (lane & 4) ? w2[jj+2] : w2[jj];
                float oth  = (lane & 4) ? w2[jj]   : w2[jj+2];
                x2[jj] = mine + __shfl_xor_sync(0xffffffffu, oth, 4);
            }
            float z;
            {
                float mine = (lane & 2) ? x2[1] : x2[0];
                float oth  = (lane & 2) ? x2[0] : x2[1];
                z = mine + __shfl_xor_sync(0xffffffffu, oth, 2);
                z += __shfl_xor_sync(0xffffffffu, z, 1);
            }
            float p0[8], p1[8];
#pragma unroll
            for (int i = 0; i < 8; i++) {
                p0[i] = __shfl_sync(0xffffffffu, z, i*2);
                p1[i] = __shfl_sync(0xffffffffu, z, 16 + i*2);
            }

            // triangular fixup, both rows
            float d0[8], d1[8];
            d0[0] = kk[0].x - p0[0];
            d1[0] = kk[0].y - p1[0];
            {
                int ix = 0;
#pragma unroll
                for (int i = 1; i < 8; i++) {
                    float a0v = kk[i].x - p0[i];
                    float a1v = kk[i].y - p1[i];
#pragma unroll
                    for (int jj = 0; jj < i; jj++) {
                        a0v -= d0[jj] * gg[ix + jj];
                        a1v -= d1[jj] * gg[ix + jj];
                    }
                    ix += i;
                    d0[i] = a0v; d1[i] = a1v;
                }
            }
            // updates (reload n from smem)
#pragma unroll
            for (int i = 0; i < 8; i++) {
                float4 n4 = *(const float4*)(nrows + i*HALF_);
                ull na = pk2(n4.x, n4.y), nb = pk2(n4.z, n4.w);
                ull D0 = pk2(d0[i], d0[i]);
                ull D1 = pk2(d1[i], d1[i]);
                s0a = ffma2(D0, na, s0a); s0b = ffma2(D0, nb, s0b);
                s1a = ffma2(D1, na, s1a); s1b = ffma2(D1, nb, s1b);
            }
        }
        __syncthreads();
        if (c + 2 < 16) issue(c + 2);
    }

    // singles t = 504..510 (chunk 15 buffer = ksm[1], rows t-480)
    {
        const float* buf = ksm[1];
        for (int t = 504; t <= 510; t++) {
            float4 n4 = *(const float4*)(buf + (t-480)*HALF_ + lane*4);
            ull na = pk2(n4.x, n4.y), nb = pk2(n4.z, n4.w);
            float2 ta = upk2(ffma2(s0b, nb, fmul2(s0a, na)));
            float p0v = ta.x + ta.y;
            float2 tb = upk2(ffma2(s1b, nb, fmul2(s1a, na)));
            float p1v = tb.x + tb.y;
#pragma unroll
            for (int o = 16; o; o >>= 1) {
                p0v += __shfl_xor_sync(0xffffffffu, p0v, o);
                p1v += __shfl_xor_sync(0xffffffffu, p1v, o);
            }
            float2 kv = *(const float2*)(kr + (size_t)t*H_ + r0);
            ull D0 = pk2(kv.x - p0v, kv.x - p0v);
            ull D1 = pk2(kv.y - p1v, kv.y - p1v);
            s0a = ffma2(D0, na, s0a); s0b = ffma2(D0, nb, s0b);
            s1a = ffma2(D1, na, s1a); s1b = ffma2(D1, nb, s1b);
        }
    }

    // final read with raw last-token key (t = 511)
    {
        float4 q4 = *(const float4*)(kr + (size_t)511*H_ + lane*4);
        ull qa = pk2(q4.x, q4.y), qb = pk2(q4.z, q4.w);
        float2 ta = upk2(ffma2(s0b, qb, fmul2(s0a, qa)));
        float p0v = ta.x + ta.y;
        float2 tb = upk2(ffma2(s1b, qb, fmul2(s1a, qa)));
        float p1v = tb.x + tb.y;
#pragma unroll
        for (int o = 16; o; o >>= 1) {
            p0v += __shfl_xor_sync(0xffffffffu, p0v, o);
            p1v += __shfl_xor_sync(0xffffffffu, p1v, o);
        }
        if (lane == 0) {
            co[b*H_ + mm*HALF_ + r0]     = p0v;
            co[b*H_ + mm*HALF_ + r0 + 1] = p1v;
        }
    }
}

// ---------------- r = c @ W_rp^T + b_rp ----------------
__global__ void rproj_kernel(const float* __restrict__ c, const float* __restrict__ W_rp,
                             const float* __restrict__ b_rp, float* __restrict__ r) {
    gdc_wait();
    int b = blockIdx.x;
    int j = threadIdx.x;
    __shared__ float cs[H_];
    cs[j] = c[b*H_ + j];
    __syncthreads();
    float acc = b_rp[j];
    const float* w = W_rp + (size_t)j*H_;
#pragma unroll 8
    for (int k = 0; k < H_; k++) acc += w[k] * cs[k];
    r[b*H_ + j] = acc;
}

// ---------------- out = r @ W_out^T + b_out: VB=64, KC=64, cp.async double-buffered ----------------
__global__ __launch_bounds__(256)
void out_kernel(const float* __restrict__ r, const float* __restrict__ W_out,
                const float* __restrict__ b_out, float* __restrict__ out) {
    const int VB = 64, KC = 64;
    __shared__ float rs[B_*H_];                  // 16 KB
    __shared__ float ws[2][VB][KC + 4];          // 34.8 KB
    int tid = threadIdx.x;
    int vl  = tid & 63;
    int bh  = tid >> 6;                          // batch quarter: 0..3
    int v   = blockIdx.x * VB + vl;

    auto wload = [&](int st, int kc) {
#pragma unroll
        for (int u = 0; u < 4; u++) {
            int unit = tid + u*256;              // 1024 float4 units
            int row = unit >> 4, c4 = (unit & 15) * 4;
            cp16(&ws[st][row][c4],
                 &W_out[(size_t)(blockIdx.x*VB + row)*H_ + kc + c4]);
        }
        asm volatile("cp.async.commit_group;\n");
    };

    gdc_wait();
    for (int e = tid*4; e < B_*H_; e += 1024) *(float4*)&rs[e] = *(const float4*)&r[e];
    wload(0, 0);

    float acc[4] = {0.f, 0.f, 0.f, 0.f};
    const int NC = H_ / KC;                      // 4 chunks
    for (int cchunk = 0; cchunk < NC; cchunk++) {
        if (cchunk + 1 < NC) {
            wload((cchunk + 1) & 1, (cchunk + 1) * KC);
            asm volatile("cp.async.wait_group 1;\n");
        } else {
            asm volatile("cp.async.wait_group 0;\n");
        }
        __syncthreads();
        const int kc = cchunk * KC;
        const int st = cchunk & 1;
#pragma unroll
        for (int k = 0; k < KC; k += 4) {
            float4 w4 = *(const float4*)&ws[st][vl][k];
#pragma unroll
            for (int b = 0; b < 4; b++) {
                float4 r4 = *(const float4*)&rs[(bh*4 + b)*H_ + kc + k];
                acc[b] += w4.x*r4.x + w4.y*r4.y + w4.z*r4.z + w4.w*r4.w;
            }
        }
        __syncthreads();
    }
    float bo = b_out[v];
#pragma unroll
    for (int b = 0; b < 4; b++) out[(size_t)(bh*4 + b)*V_ + v] = acc[b] + bo;
}

// ---------------- PDL launch helper ----------------
template<typename F, typename... Args>
static inline void launch_pdl(F func, dim3 grid, dim3 block, size_t smem, Args... args) {
    cudaLaunchAttribute attr[1];
    attr[0].id = cudaLaunchAttributeProgrammaticStreamSerialization;
    attr[0].val.programmaticStreamSerializationAllowed = 1;
    cudaLaunchConfig_t cfg = {};
    cfg.gridDim = grid;
    cfg.blockDim = block;
    cfg.dynamicSmemBytes = smem;
    cfg.stream = 0;
    cfg.attrs = attr;
    cfg.numAttrs = 1;
    cudaLaunchKernelEx(&cfg, func, args...);
}

// ---------------- launch ----------------
extern "C" void kernel_launch(void* const* d_in, const int* in_sizes, int n_in,
                              void* d_out, int out_size) {
    const int*   seq   = (const int*)  d_in[0];
    const float* embed = (const float*)d_in[1];
    const float* W1    = (const float*)d_in[2];
    const float* b1    = (const float*)d_in[3];
    const float* W2    = (const float*)d_in[4];
    const float* b2    = (const float*)d_in[5];
    const float* gamma = (const float*)d_in[6];
    const float* beta  = (const float*)d_in[7];
    const float* W_sem = (const float*)d_in[8];
    const float* W_epi = (const float*)d_in[9];
    const float* W_rp  = (const float*)d_in[10];
    const float* b_rp  = (const float*)d_in[11];
    const float* W_out = (const float*)d_in[12];
    const float* b_out = (const float*)d_in[13];
    float* out = (float*)d_out;

    float *x, *kraw, *kns, *kne, *gram, *c, *r;
    bf16 *hh, *hl, *W1h, *W1l, *W2h, *W2l, *Wkh, *Wkl, *hidh, *hidl, *hnh, *hnl;
    cudaGetSymbolAddress((void**)&hh,   g_hh);
    cudaGetSymbolAddress((void**)&hl,   g_hl);
    cudaGetSymbolAddress((void**)&W1h,  g_W1h);
    cudaGetSymbolAddress((void**)&W1l,  g_W1l);
    cudaGetSymbolAddress((void**)&W2h,  g_W2h);
    cudaGetSymbolAddress((void**)&W2l,  g_W2l);
    cudaGetSymbolAddress((void**)&Wkh,  g_Wkh);
    cudaGetSymbolAddress((void**)&Wkl,  g_Wkl);
    cudaGetSymbolAddress((void**)&hidh, g_hidh);
    cudaGetSymbolAddress((void**)&hidl, g_hidl);
    cudaGetSymbolAddress((void**)&x,    g_x);
    cudaGetSymbolAddress((void**)&hnh,  g_hnh);
    cudaGetSymbolAddress((void**)&hnl,  g_hnl);
    cudaGetSymbolAddress((void**)&kraw, g_kraw);
    cudaGetSymbolAddress((void**)&kns,  g_kns);
    cudaGetSymbolAddress((void**)&kne,  g_kne);
    cudaGetSymbolAddress((void**)&gram, g_gram);
    cudaGetSymbolAddress((void**)&c,    g_c);
    cudaGetSymbolAddress((void**)&r,    g_r);

    cudaFuncSetAttribute(gemm3_kernel<0>, cudaFuncAttributeMaxDynamicSharedMemorySize, GSMEM);
    cudaFuncSetAttribute(gemm3_kernel<1>, cudaFuncAttributeMaxDynamicSharedMemorySize, GSMEM);
    cudaFuncSetAttribute(gemm3_kernel<2>, cudaFuncAttributeMaxDynamicSharedMemorySize, GSMEM);

    launch_pdl(prep_kernel, dim3(1280 + TOK/4), dim3(256), 0,
               seq, embed, W1, W2, W_sem, W_epi,
               W1h, W1l, W2h, W2l, Wkh, Wkl, hh, hl);
    launch_pdl(gemm3_kernel<1>, dim3(H2_/GBN, TOK/GBM), dim3(256), (size_t)GSMEM,
               (const bf16*)hh, (const bf16*)hl, (const bf16*)W1h, (const bf16*)W1l,
               b1, (const bf16*)nullptr, (const bf16*)nullptr,
               (float*)nullptr, hidh, hidl, TOK, H2_, H_);
    launch_pdl(gemm3_kernel<2>, dim3(H_/GBN, TOK/GBM), dim3(256), (size_t)GSMEM,
               (const bf16*)hidh, (const bf16*)hidl, (const bf16*)W2h, (const bf16*)W2l,
               b2, (const bf16*)hh, (const bf16*)hl,
               x, (bf16*)nullptr, (bf16*)nullptr, TOK, H_, H2_);
    launch_pdl(ln_kernel, dim3(TOK/16), dim3(256), 0,
               (const float*)x, hnh, hnl, gamma, beta);
    launch_pdl(gemm3_kernel<0>, dim3(H_/GBN, TOK/GBM), dim3(256), (size_t)GSMEM,
               (const bf16*)hnh, (const bf16*)hnl, (const bf16*)Wkh, (const bf16*)Wkl,
               (const float*)nullptr, (const bf16*)nullptr, (const bf16*)nullptr,
               kraw, (bf16*)nullptr, (bf16*)nullptr, TOK, H_, H_);
    launch_pdl(knorm_gram_kernel, dim3(256), dim3(256), 0,
               (const float*)kraw, kns, kne, gram);
    launch_pdl(scan_kernel, dim3(256), dim3(256), 0,
               (const float*)kraw, (const float*)kns, (const float*)kne,
               (const float*)gram, c);
    launch_pdl(rproj_kernel, dim3(B_), dim3(H_), 0,
               (const float*)c, W_rp, b_rp, r);
    launch_pdl(out_kernel, dim3(V_/64), dim3(256), 0,
               (const float*)r, W_out, b_out, out);
}

// round 16
// speedup vs baseline: 1.0262x; 1.0262x over previous
#include <cuda_runtime.h>
#include <cuda_bf16.h>
#include <cstdint>

#define B_    16
#define L_    512
#define H_    256
#define V_    32000
#define HALF_ 128
#define TOK   (B_*L_)   // 8192
#define H2_   (2*H_)    // 512
#define NBLK  127       // 4-step scan blocks at t0=4k (127*4=508) + 3 singles = 511

typedef __nv_bfloat16 bf16;
typedef unsigned long long ull;

// ---------------- scratch (device globals) ----------------
__device__ __align__(16) bf16  g_hh [TOK*H_];
__device__ __align__(16) bf16  g_hl [TOK*H_];
__device__ __align__(16) bf16  g_W1h[H2_*H_], g_W1l[H2_*H_];
__device__ __align__(16) bf16  g_W2h[H_*H2_], g_W2l[H_*H2_];
__device__ __align__(16) bf16  g_Wkh[H_*H_],  g_Wkl[H_*H_];
__device__ __align__(16) bf16  g_hidh[TOK*H2_], g_hidl[TOK*H2_];
__device__ __align__(16) float g_x  [TOK*H_];
__device__ __align__(16) bf16  g_hnh[TOK*H_], g_hnl[TOK*H_];
__device__ __align__(16) float g_kraw[TOK*H_];        // [ks | ke] per token, stride 256
__device__ __align__(16) float g_kns[B_*512*HALF_];   // padded to 512 timesteps
__device__ __align__(16) float g_kne[B_*512*HALF_];
__device__ __align__(16) float g_gram[B_*2*NBLK*8];   // {g01,g02,g03,g12,g13,g23,0,0}
__device__ __align__(16) float g_c  [B_*H_];
__device__ __align__(16) float g_r  [B_*H_];
__device__ float g_sink[512];

// ---------------- helpers ----------------
__device__ __forceinline__ void gdc_wait() {
    asm volatile("griddepcontrol.wait;" ::: "memory");
}
__device__ __forceinline__ void gdc_launch() {
    asm volatile("griddepcontrol.launch_dependents;" ::: "memory");
}
__device__ __forceinline__ void split2(float v, bf16& hi, bf16& lo) {
    hi = __float2bfloat16(v);
    lo = __float2bfloat16(v - __bfloat162float(hi));
}
__device__ __forceinline__ uint32_t s2u(const void* p) {
    return (uint32_t)__cvta_generic_to_shared(p);
}
__device__ __forceinline__ void cp16(void* s, const void* g) {
    asm volatile("cp.async.cg.shared.global [%0], [%1], 16;\n" :: "r"(s2u(s)), "l"(g));
}
// packed f32x2
__device__ __forceinline__ ull pk2(float a, float b) {
    ull r; asm("mov.b64 %0, {%1, %2};" : "=l"(r) : "f"(a), "f"(b)); return r;
}
__device__ __forceinline__ float2 upk2(ull v) {
    float2 f; asm("mov.b64 {%0, %1}, %2;" : "=f"(f.x), "=f"(f.y) : "l"(v)); return f;
}
__device__ __forceinline__ ull ffma2(ull a, ull b, ull c) {
    ull d; asm("fma.rn.f32x2 %0, %1, %2, %3;" : "=l"(d) : "l"(a), "l"(b), "l"(c)); return d;
}
__device__ __forceinline__ ull fmul2(ull a, ull b) {
    ull d; asm("mul.rn.f32x2 %0, %1, %2;" : "=l"(d) : "l"(a), "l"(b)); return d;
}

// ---------------- merged prep: weight splits + embedding gather ----------------
__global__ void prep_kernel(const int* __restrict__ seq, const float* __restrict__ embed,
                            const float* __restrict__ W1, const float* __restrict__ W2,
                            const float* __restrict__ Wsem, const float* __restrict__ Wepi,
                            bf16* __restrict__ W1h, bf16* __restrict__ W1l,
                            bf16* __restrict__ W2h, bf16* __restrict__ W2l,
                            bf16* __restrict__ Wkh, bf16* __restrict__ Wkl,
                            bf16* __restrict__ hh, bf16* __restrict__ hl) {
    gdc_wait();
    int bx = blockIdx.x, tid = threadIdx.x;
    if (bx < 1280) {
        int i = bx * 256 + tid;
        const float* src; bf16 *hi, *lo; int off;
        if (i < 131072)      { src = W1;   hi = W1h; lo = W1l; off = i; }
        else if (i < 262144) { src = W2;   hi = W2h; lo = W2l; off = i - 131072; }
        else if (i < 294912) { src = Wsem; hi = Wkh; lo = Wkl; off = i - 262144; }
        else                 { src = Wepi; hi = Wkh + 32768; lo = Wkl + 32768; off = i - 294912; }
        bf16 a, b; split2(src[off], a, b);
        hi[off] = a; lo[off] = b;
    } else {
        int tok = (bx - 1280) * 4 + (tid >> 6);
        int col = (tid & 63) * 4;
        int s = __ldg(seq + tok);
        float4 v = *(const float4*)&embed[(size_t)s * H_ + col];
        bf16 h4[4], l4[4];
        split2(v.x, h4[0], l4[0]); split2(v.y, h4[1], l4[1]);
        split2(v.z, h4[2], l4[2]); split2(v.w, h4[3], l4[3]);
        *(uint2*)&hh[(size_t)tok * H_ + col] = *(uint2*)h4;
        *(uint2*)&hl[(size_t)tok * H_ + col] = *(uint2*)l4;
    }
}

// ---------------- bf16x3 split-GEMM, 128x64 tiles, term-major MMA order ----------------
#define GBM 128
#define GBN 64
#define GBK 32
#define SLD (GBK + 8)
#define ATILE (GBM * SLD)
#define BTILE (GBN * SLD)
#define GSMEM ((4*ATILE + 4*BTILE) * 2)   // 61440

#define MMA_BF16(d, a, b) asm volatile( \
    "mma.sync.aligned.m16n8k16.row.col.f32.bf16.bf16.f32 " \
    "{%0,%1,%2,%3},{%4,%5,%6,%7},{%8,%9},{%0,%1,%2,%3};" \
    : "+f"(d[0]), "+f"(d[1]), "+f"(d[2]), "+f"(d[3]) \
    : "r"(a[0]), "r"(a[1]), "r"(a[2]), "r"(a[3]), "r"(b[0]), "r"(b[1]))

#define LDSM4(r0, r1, r2, r3, addr) asm volatile( \
    "ldmatrix.sync.aligned.m8n8.x4.shared.b16 {%0,%1,%2,%3}, [%4];" \
    : "=r"(r0), "=r"(r1), "=r"(r2), "=r"(r3) : "r"(addr))

template<int EPI>
__global__ __launch_bounds__(256, 2)
void gemm3_kernel(const bf16* __restrict__ Ah, const bf16* __restrict__ Al,
                  const bf16* __restrict__ Bh, const bf16* __restrict__ Bl,
                  const float* __restrict__ bias, const bf16* __restrict__ Rh,
                  const bf16* __restrict__ Rl,
                  float* __restrict__ Cf, bf16* __restrict__ Ch, bf16* __restrict__ Cl,
                  int M, int N, int K) {
    extern __shared__ bf16 smem[];
    bf16* As_h = smem;
    bf16* As_l = smem + 2*ATILE;
    bf16* Bs_h = smem + 4*ATILE;
    bf16* Bs_l = smem + 4*ATILE + 2*BTILE;

    const int tid  = threadIdx.x;
    const int wid  = tid >> 5;
    const int lane = tid & 31;
    const int wm   = (wid & 3) * 32;
    const int wn   = (wid >> 2) * 32;
    const int r    = lane >> 2;
    const int q    = lane & 3;
    const int m0   = blockIdx.y * GBM;
    const int n0   = blockIdx.x * GBN;

    const int aoff = (wm + (lane & 15)) * SLD + ((lane >> 4) * 8);
    const int boff = (wn + ((lane >> 4) * 8) + (lane & 7)) * SLD + (((lane >> 3) & 1) * 8);

    float c[2][4][4];
#pragma unroll
    for (int mt = 0; mt < 2; mt++)
#pragma unroll
        for (int nt = 0; nt < 4; nt++)
#pragma unroll
            for (int e = 0; e < 4; e++) c[mt][nt][e] = 0.f;

    auto load_stage = [&](int st, int k0) {
#pragma unroll
        for (int i = tid; i < 512; i += 256) {
            int row = i >> 2, kc = (i & 3) * 8;
            size_t ga = (size_t)(m0 + row) * K + k0 + kc;
            int so = st * ATILE + row * SLD + kc;
            cp16(As_h + so, Ah + ga);
            cp16(As_l + so, Al + ga);
        }
        {
            int i = tid;
            int row = i >> 2, kc = (i & 3) * 8;
            size_t gb = (size_t)(n0 + row) * K + k0 + kc;
            int so = st * BTILE + row * SLD + kc;
            cp16(Bs_h + so, Bh + gb);
            cp16(Bs_l + so, Bl + gb);
        }
        asm volatile("cp.async.commit_group;\n");
    };

    gdc_wait();
    const int T = K / GBK;
    load_stage(0, 0);

    for (int t = 0; t < T; t++) {
        if (t + 1 < T) {
            load_stage((t + 1) & 1, (t + 1) * GBK);
            asm volatile("cp.async.wait_group 1;\n");
        } else {
            asm volatile("cp.async.wait_group 0;\n");
        }
        __syncthreads();

        const uint32_t aBh = s2u(As_h + (t & 1) * ATILE + aoff);
        const uint32_t aBl = s2u(As_l + (t & 1) * ATILE + aoff);
        const uint32_t bBh = s2u(Bs_h + (t & 1) * BTILE + boff);
        const uint32_t bBl = s2u(Bs_l + (t & 1) * BTILE + boff);

#pragma unroll
        for (int kk = 0; kk < GBK; kk += 16) {
            const uint32_t ko = kk * 2;
            uint32_t Afh[2][4], Afl[2][4], Bfh[4][2], Bfl[4][2];
#pragma unroll
            for (int mt = 0; mt < 2; mt++) {
                LDSM4(Afh[mt][0], Afh[mt][1], Afh[mt][2], Afh[mt][3],
                      aBh + (uint32_t)(mt * 16 * SLD * 2) + ko);
                LDSM4(Afl[mt][0], Afl[mt][1], Afl[mt][2], Afl[mt][3],
                      aBl + (uint32_t)(mt * 16 * SLD * 2) + ko);
            }
#pragma unroll
            for (int ntp = 0; ntp < 2; ntp++) {
                LDSM4(Bfh[2*ntp][0], Bfh[2*ntp][1], Bfh[2*ntp+1][0], Bfh[2*ntp+1][1],
                      bBh + (uint32_t)(ntp * 16 * SLD * 2) + ko);
                LDSM4(Bfl[2*ntp][0], Bfl[2*ntp][1], Bfl[2*ntp+1][0], Bfl[2*ntp+1][1],
                      bBl + (uint32_t)(ntp * 16 * SLD * 2) + ko);
            }
#pragma unroll
            for (int mt = 0; mt < 2; mt++)
#pragma unroll
                for (int nt = 0; nt < 4; nt++)
                    MMA_BF16(c[mt][nt], Afh[mt], Bfh[nt]);
#pragma unroll
            for (int mt = 0; mt < 2; mt++)
#pragma unroll
                for (int nt = 0; nt < 4; nt++)
                    MMA_BF16(c[mt][nt], Afh[mt], Bfl[nt]);
#pragma unroll
            for (int mt = 0; mt < 2; mt++)
#pragma unroll
                for (int nt = 0; nt < 4; nt++)
                    MMA_BF16(c[mt][nt], Afl[mt], Bfh[nt]);
        }
        __syncthreads();
    }

#pragma unroll
    for (int mt = 0; mt < 2; mt++)
#pragma unroll
        for (int nt = 0; nt < 4; nt++) {
            int gm = m0 + wm + mt*16 + r;
            int gn = n0 + wn + nt*8 + q*2;
#pragma unroll
            for (int half = 0; half < 2; half++) {
                int m = gm + half*8;
                float v0 = c[mt][nt][half*2 + 0];
                float v1 = c[mt][nt][half*2 + 1];
                size_t o = (size_t)m * N + gn;
                if (EPI == 1) {
                    v0 = fmaxf(v0 + bias[gn],     0.f);
                    v1 = fmaxf(v1 + bias[gn + 1], 0.f);
                    bf16 h0, l0, h1, l1;
                    split2(v0, h0, l0); split2(v1, h1, l1);
                    __nv_bfloat162 ph; ph.x = h0; ph.y = h1;
                    __nv_bfloat162 pl; pl.x = l0; pl.y = l1;
                    *(__nv_bfloat162*)&Ch[o] = ph;
                    *(__nv_bfloat162*)&Cl[o] = pl;
                } else if (EPI == 2) {
                    __nv_bfloat162 rh = *(const __nv_bfloat162*)&Rh[o];
                    __nv_bfloat162 rl = *(const __nv_bfloat162*)&Rl[o];
                    v0 += bias[gn]     + __bfloat162float(rh.x) + __bfloat162float(rl.x);
                    v1 += bias[gn + 1] + __bfloat162float(rh.y) + __bfloat162float(rl.y);
                    float2 p; p.x = v0; p.y = v1;
                    *(float2*)&Cf[o] = p;
                } else {
                    float2 p; p.x = v0; p.y = v1;
                    *(float2*)&Cf[o] = p;
                }
            }
        }
}

// ---------------- LayerNorm: one warp per row, output bf16 split ----------------
__global__ void ln_kernel(const float* __restrict__ x, bf16* __restrict__ hh,
                          bf16* __restrict__ hl, const float* __restrict__ gamma,
                          const float* __restrict__ beta) {
    gdc_wait();
    int row  = blockIdx.x * 8 + (threadIdx.x >> 5);
    int lane = threadIdx.x & 31;
    const float* xr = x + (size_t)row * H_ + lane * 8;
    float4 v0 = *(const float4*)xr;
    float4 v1 = *(const float4*)(xr + 4);
    float s  = v0.x+v0.y+v0.z+v0.w+v1.x+v1.y+v1.z+v1.w;
    float ss = v0.x*v0.x+v0.y*v0.y+v0.z*v0.z+v0.w*v0.w
             + v1.x*v1.x+v1.y*v1.y+v1.z*v1.z+v1.w*v1.w;
#pragma unroll
    for (int o = 16; o; o >>= 1) {
        s  += __shfl_xor_sync(0xffffffffu, s,  o);
        ss += __shfl_xor_sync(0xffffffffu, ss, o);
    }
    float mu  = s * (1.0f / H_);
    float var = ss * (1.0f / H_) - mu * mu;
    float inv = rsqrtf(var + 1e-5f);
    float4 g0 = *(const float4*)(gamma + lane*8);
    float4 g1 = *(const float4*)(gamma + lane*8 + 4);
    float4 b0 = *(const float4*)(beta  + lane*8);
    float4 b1 = *(const float4*)(beta  + lane*8 + 4);
    float y[8] = {
        (v0.x-mu)*inv*g0.x + b0.x, (v0.y-mu)*inv*g0.y + b0.y,
        (v0.z-mu)*inv*g0.z + b0.z, (v0.w-mu)*inv*g0.w + b0.w,
        (v1.x-mu)*inv*g1.x + b1.x, (v1.y-mu)*inv*g1.y + b1.y,
        (v1.z-mu)*inv*g1.z + b1.z, (v1.w-mu)*inv*g1.w + b1.w };
    bf16 oh[8], ol[8];
#pragma unroll
    for (int i = 0; i < 8; i++) split2(y[i], oh[i], ol[i]);
    *(uint4*)&hh[(size_t)row * H_ + lane*8] = *(uint4*)oh;
    *(uint4*)&hl[(size_t)row * H_ + lane*8] = *(uint4*)ol;
}

// ---------------- W_out L2 prefetch (overlaps knorm/scan/rproj) ----------------
__global__ void prefetch_kernel(const float* __restrict__ W_out) {
    gdc_wait();        // preserve upstream dependency (gemm3<0> must finish)
    gdc_launch();      // release dependents immediately -> overlap with streaming below
    float acc = 0.f;
    size_t stride = (size_t)gridDim.x * blockDim.x;
    const float4* p = (const float4*)W_out;
    for (size_t i = (size_t)blockIdx.x * blockDim.x + threadIdx.x;
         i < (size_t)V_ * H_ / 4; i += stride) {
        float4 v = __ldg(p + i);
        acc += v.x + v.y + v.z + v.w;
    }
    if (acc == 123456789.0f) g_sink[blockIdx.x & 511] = acc;   // never taken; keeps loads
}

// ---------------- fused key-normalize + Gram ----------------
__global__ void knorm_gram_kernel(const float* __restrict__ kraw, float* __restrict__ kns,
                                  float* __restrict__ kne, float* __restrict__ gram) {
    gdc_wait();
    int w = blockIdx.x * 8 + (threadIdx.x >> 5);   // 0..4095
    int lane = threadIdx.x & 31;
    int grp = w & 127;            // 4-step group
    int pr  = w >> 7;             // pair 0..31
    int mm = pr & 1, b = pr >> 1;

    float4 v[4];
    float ss[4];
#pragma unroll
    for (int i = 0; i < 4; i++) {
        int t = grp*4 + i;
        if (t < 511) v[i] = *(const float4*)(kraw + ((size_t)(b*L_ + t))*H_ + mm*HALF_ + lane*4);
        else         v[i] = make_float4(0.f, 0.f, 0.f, 0.f);
        ss[i] = v[i].x*v[i].x + v[i].y*v[i].y + v[i].z*v[i].z + v[i].w*v[i].w;
    }
#pragma unroll
    for (int o = 16; o; o >>= 1) {
#pragma unroll
        for (int i = 0; i < 4; i++) ss[i] += __shfl_xor_sync(0xffffffffu, ss[i], o);
    }
    float4 n[4];
    float* dstb = (mm ? kne : kns) + (size_t)b*512*HALF_;
#pragma unroll
    for (int i = 0; i < 4; i++) {
        float inv = 1.0f / fmaxf(sqrtf(ss[i]), 1e-12f);
        n[i].x = v[i].x*inv; n[i].y = v[i].y*inv; n[i].z = v[i].z*inv; n[i].w = v[i].w*inv;
        int t = grp*4 + i;
        if (t < 511) *(float4*)(dstb + (size_t)t*HALF_ + lane*4) = n[i];
    }
    if (grp >= NBLK) return;
    float d01 = n[0].x*n[1].x + n[0].y*n[1].y + n[0].z*n[1].z + n[0].w*n[1].w;
    float d02 = n[0].x*n[2].x + n[0].y*n[2].y + n[0].z*n[2].z + n[0].w*n[2].w;
    float d03 = n[0].x*n[3].x + n[0].y*n[3].y + n[0].z*n[3].z + n[0].w*n[3].w;
    float d12 = n[1].x*n[2].x + n[1].y*n[2].y + n[1].z*n[2].z + n[1].w*n[2].w;
    float d13 = n[1].x*n[3].x + n[1].y*n[3].y + n[1].z*n[3].z + n[1].w*n[3].w;
    float d23 = n[2].x*n[3].x + n[2].y*n[3].y + n[2].z*n[3].z + n[2].w*n[3].w;
#pragma unroll
    for (int o = 16; o; o >>= 1) {
        d01 += __shfl_xor_sync(0xffffffffu, d01, o);
        d02 += __shfl_xor_sync(0xffffffffu, d02, o);
        d03 += __shfl_xor_sync(0xffffffffu, d03, o);
        d12 += __shfl_xor_sync(0xffffffffu, d12, o);
        d13 += __shfl_xor_sync(0xffffffffu, d13, o);
        d23 += __shfl_xor_sync(0xffffffffu, d23, o);
    }
    if (lane == 0) {
        float* gp = gram + (size_t)(pr*NBLK + grp) * 8;
        float4 a; a.x = d01; a.y = d02; a.z = d03; a.w = d12;
        float4 bb; bb.x = d13; bb.y = d23; bb.z = 0.f; bb.w = 0.f;
        *(float4*)gp = a;
        *(float4*)(gp + 4) = bb;
    }
}

// ---------------- blocked delta-rule scan: SMEM-staged, 2 rows/warp ----------------
__global__ __launch_bounds__(256)
void scan_kernel(const float* __restrict__ kraw,
                 const float* __restrict__ kns, const float* __restrict__ kne,
                 const float* __restrict__ gram, float* __restrict__ co) {
    __shared__ float ksm[2][32*HALF_];   // 2 x 16KB

    const int bx = blockIdx.x;
    const int rg = bx & 7;
    const int pr = bx >> 3;              // pair 0..31
    const int mm = pr & 1, b = pr >> 1;
    const int w = threadIdx.x >> 5, lane = threadIdx.x & 31;
    const int r0 = rg*16 + w*2;          // rows r0, r0+1

    const float* kn = (mm ? kne : kns) + (size_t)b*512*HALF_;
    const float* kr = kraw + (size_t)b*L_*H_ + mm*HALF_;
    const float* gr = gram + (size_t)pr*NBLK*8;

    auto issue = [&](int cc) {
        const float* src = kn + (size_t)cc*32*HALF_;
        float* dst = ksm[cc & 1];
#pragma unroll
        for (int j = 0; j < 4; j++) {
            int pos = threadIdx.x + j*256;
            cp16(dst + pos*4, src + pos*4);
        }
        asm volatile("cp.async.commit_group;\n");
    };

    ull s0a = 0, s0b = 0, s1a = 0, s1b = 0;

    gdc_wait();
    issue(0); issue(1);

    for (int c = 0; c < 16; c++) {
        if (c == 15) asm volatile("cp.async.wait_group 0;\n");
        else         asm volatile("cp.async.wait_group 1;\n");
        __syncthreads();
        const float* buf = ksm[c & 1];
        const int nb = (c == 15) ? 7 : 8;
        for (int j = 0; j < nb; j++) {
            const int blk = c*8 + j;
            const int ts = j*4;
            ull na[4], nb2[4];
#pragma unroll
            for (int i = 0; i < 4; i++) {
                float4 n4 = *(const float4*)(buf + (ts+i)*HALF_ + lane*4);
                na[i] = pk2(n4.x, n4.y); nb2[i] = pk2(n4.z, n4.w);
            }
            float4 gv0 = *(const float4*)(gr + blk*8);
            float4 gv1 = *(const float4*)(gr + blk*8 + 4);
            const float* kb = kr + (size_t)(blk*4)*H_ + r0;
            float k00 = __ldg(kb),         k01 = __ldg(kb + H_);
            float k02 = __ldg(kb + 2*H_),  k03 = __ldg(kb + 3*H_);
            float k10 = __ldg(kb + 1),     k11 = __ldg(kb + H_ + 1);
            float k12 = __ldg(kb + 2*H_+1),k13 = __ldg(kb + 3*H_ + 1);

            float v[8];
#pragma unroll
            for (int i = 0; i < 4; i++) {
                float2 ta = upk2(ffma2(s0b, nb2[i], fmul2(s0a, na[i])));
                v[i]   = ta.x + ta.y;
                float2 tb = upk2(ffma2(s1b, nb2[i], fmul2(s1a, na[i])));
                v[4+i] = tb.x + tb.y;
            }
            float u0[4];
#pragma unroll
            for (int jj = 0; jj < 4; jj++) {
                float lo = v[jj], hi = v[jj+4];
                float mine = (lane & 16) ? hi : lo;
                float oth  = (lane & 16) ? lo : hi;
                u0[jj] = mine + __shfl_xor_sync(0xffffffffu, oth, 16);
            }
            float w0[2];
#pragma unroll
            for (int jj = 0; jj < 2; jj++) {
                float mine = (lane & 8) ? u0[jj+2] : u0[jj];
                float oth  = (lane & 8) ? u0[jj]   : u0[jj+2];
                w0[jj] = mine + __shfl_xor_sync(0xffffffffu, oth, 8);
            }
            {
                float mine = (lane & 4) ? w0[1] : w0[0];
                float oth  = (lane & 4) ? w0[0] : w0[1];
                float z = mine + __shfl_xor_sync(0xffffffffu, oth, 4);
                z += __shfl_xor_sync(0xffffffffu, z, 2);
                z += __shfl_xor_sync(0xffffffffu, z, 1);
                float p00 = __shfl_sync(0xffffffffu, z, 0);
                float p01 = __shfl_sync(0xffffffffu, z, 4);
                float p02 = __shfl_sync(0xffffffffu, z, 8);
                float p03 = __shfl_sync(0xffffffffu, z, 12);
                float p10 = __shfl_sync(0xffffffffu, z, 16);
                float p11 = __shfl_sync(0xffffffffu, z, 20);
                float p12 = __shfl_sync(0xffffffffu, z, 24);
                float p13 = __shfl_sync(0xffffffffu, z, 28);
                float d00 = k00 - p00;
                float d01 = k01 - p01 - d00*gv0.x;
                float d02 = k02 - p02 - d00*gv0.y - d01*gv0.w;
                float d03 = k03 - p03 - d00*gv0.z - d01*gv1.x - d02*gv1.y;
                float d10 = k10 - p10;
                float d11 = k11 - p11 - d10*gv0.x;
                float d12v= k12 - p12 - d10*gv0.y - d11*gv0.w;
                float d13v= k13 - p13 - d10*gv0.z - d11*gv1.x - d12v*gv1.y;
                ull D;
                D = pk2(d00, d00); s0a = ffma2(D, na[0], s0a); s0b = ffma2(D, nb2[0], s0b);
                D = pk2(d01, d01); s0a = ffma2(D, na[1], s0a); s0b = ffma2(D, nb2[1], s0b);
                D = pk2(d02, d02); s0a = ffma2(D, na[2], s0a); s0b = ffma2(D, nb2[2], s0b);
                D = pk2(d03, d03); s0a = ffma2(D, na[3], s0a); s0b = ffma2(D, nb2[3], s0b);
                D = pk2(d10, d10); s1a = ffma2(D, na[0], s1a); s1b = ffma2(D, nb2[0], s1b);
                D = pk2(d11, d11); s1a = ffma2(D, na[1], s1a); s1b = ffma2(D, nb2[1], s1b);
                D = pk2(d12v,d12v);s1a = ffma2(D, na[2], s1a); s1b = ffma2(D, nb2[2], s1b);
                D = pk2(d13v,d13v);s1a = ffma2(D, na[3], s1a); s1b = ffma2(D, nb2[3], s1b);
            }
        }
        __syncthreads();
        if (c + 2 < 16) issue(c + 2);
    }

    // singles t = 508..510 (chunk 15 buffer = ksm[1])
    {
        const float* buf = ksm[1];
        for (int t = 508; t <= 510; t++) {
            float4 n4 = *(const float4*)(buf + (t-480)*HALF_ + lane*4);
            ull na = pk2(n4.x, n4.y), nb2 = pk2(n4.z, n4.w);
            float2 ta = upk2(ffma2(s0b, nb2, fmul2(s0a, na)));
            float p0 = ta.x + ta.y;
            float2 tb = upk2(ffma2(s1b, nb2, fmul2(s1a, na)));
            float p1 = tb.x + tb.y;
#pragma unroll
            for (int o = 16; o; o >>= 1) {
                p0 += __shfl_xor_sync(0xffffffffu, p0, o);
                p1 += __shfl_xor_sync(0xffffffffu, p1, o);
            }
            float k0v = __ldg(kr + (size_t)t*H_ + r0);
            float k1v = __ldg(kr + (size_t)t*H_ + r0 + 1);
            ull D0 = pk2(k0v - p0, k0v - p0);
            ull D1 = pk2(k1v - p1, k1v - p1);
            s0a = ffma2(D0, na, s0a); s0b = ffma2(D0, nb2, s0b);
            s1a = ffma2(D1, na, s1a); s1b = ffma2(D1, nb2, s1b);
        }
    }

    // final read with raw last-token key (t = 511)
    {
        float4 q4 = *(const float4*)(kr + (size_t)511*H_ + lane*4);
        ull qa = pk2(q4.x, q4.y), qb = pk2(q4.z, q4.w);
        float2 ta = upk2(ffma2(s0b, qb, fmul2(s0a, qa)));
        float p0 = ta.x + ta.y;
        float2 tb = upk2(ffma2(s1b, qb, fmul2(s1a, qa)));
        float p1 = tb.x + tb.y;
#pragma unroll
        for (int o = 16; o; o >>= 1) {
            p0 += __shfl_xor_sync(0xffffffffu, p0, o);
            p1 += __shfl_xor_sync(0xffffffffu, p1, o);
        }
        if (lane == 0) {
            co[b*H_ + mm*HALF_ + r0]     = p0;
            co[b*H_ + mm*HALF_ + r0 + 1] = p1;
        }
    }
}

// ---------------- r = c @ W_rp^T + b_rp ----------------
__global__ void rproj_kernel(const float* __restrict__ c, const float* __restrict__ W_rp,
                             const float* __restrict__ b_rp, float* __restrict__ r) {
    gdc_wait();
    int b = blockIdx.x;
    int j = threadIdx.x;
    __shared__ float cs[H_];
    cs[j] = c[b*H_ + j];
    __syncthreads();
    float acc = b_rp[j];
    const float* w = W_rp + (size_t)j*H_;
#pragma unroll 8
    for (int k = 0; k < H_; k++) acc += w[k] * cs[k];
    r[b*H_ + j] = acc;
}

// ---------------- out = r @ W_out^T + b_out: VB=64, cp.async double-buffered W ----------------
__global__ __launch_bounds__(256)
void out_kernel(const float* __restrict__ r, const float* __restrict__ W_out,
                const float* __restrict__ b_out, float* __restrict__ out) {
    const int VB = 64, KC = 32;
    __shared__ float rs[B_*H_];                  // 16 KB
    __shared__ float ws[2][VB][KC + 4];
    int tid = threadIdx.x;
    int vl  = tid & 63;
    int bh  = tid >> 6;                          // batch quarter: 0..3
    int v   = blockIdx.x * VB + vl;

    auto wload = [&](int st, int kc) {
#pragma unroll
        for (int u = 0; u < 2; u++) {
            int unit = tid + u*256;
            int row = unit >> 3, c4 = (unit & 7) * 4;
            cp16(&ws[st][row][c4],
                 &W_out[(size_t)(blockIdx.x*VB + row)*H_ + kc + c4]);
        }
        asm volatile("cp.async.commit_group;\n");
    };

    gdc_wait();
    for (int e = tid*4; e < B_*H_; e += 1024) *(float4*)&rs[e] = *(const float4*)&r[e];
    wload(0, 0);

    float acc[4] = {0.f, 0.f, 0.f, 0.f};
    const int NC = H_ / KC;                      // 8 chunks
    for (int cchunk = 0; cchunk < NC; cchunk++) {
        if (cchunk + 1 < NC) {
            wload((cchunk + 1) & 1, (cchunk + 1) * KC);
            asm volatile("cp.async.wait_group 1;\n");
        } else {
            asm volatile("cp.async.wait_group 0;\n");
        }
        __syncthreads();
        const int kc = cchunk * KC;
        const int st = cchunk & 1;
#pragma unroll
        for (int k = 0; k < KC; k += 4) {
            float4 w4 = *(const float4*)&ws[st][vl][k];
#pragma unroll
            for (int b = 0; b < 4; b++) {
                float4 r4 = *(const float4*)&rs[(bh*4 + b)*H_ + kc + k];
                acc[b] += w4.x*r4.x + w4.y*r4.y + w4.z*r4.z + w4.w*r4.w;
            }
        }
        __syncthreads();
    }
    float bo = b_out[v];
#pragma unroll
    for (int b = 0; b < 4; b++) out[(size_t)(bh*4 + b)*V_ + v] = acc[b] + bo;
}

// ---------------- PDL launch helper ----------------
template<typename F, typename... Args>
static inline void launch_pdl(F func, dim3 grid, dim3 block, size_t smem, Args... args) {
    cudaLaunchAttribute attr[1];
    attr[0].id = cudaLaunchAttributeProgrammaticStreamSerialization;
    attr[0].val.programmaticStreamSerializationAllowed = 1;
    cudaLaunchConfig_t cfg = {};
    cfg.gridDim = grid;
    cfg.blockDim = block;
    cfg.dynamicSmemBytes = smem;
    cfg.stream = 0;
    cfg.attrs = attr;
    cfg.numAttrs = 1;
    cudaLaunchKernelEx(&cfg, func, args...);
}

// ---------------- launch ----------------
extern "C" void kernel_launch(void* const* d_in, const int* in_sizes, int n_in,
                              void* d_out, int out_size) {
    const int*   seq   = (const int*)  d_in[0];
    const float* embed = (const float*)d_in[1];
    const float* W1    = (const float*)d_in[2];
    const float* b1    = (const float*)d_in[3];
    const float* W2    = (const float*)d_in[4];
    const float* b2    = (const float*)d_in[5];
    const float* gamma = (const float*)d_in[6];
    const float* beta  = (const float*)d_in[7];
    const float* W_sem = (const float*)d_in[8];
    const float* W_epi = (const float*)d_in[9];
    const float* W_rp  = (const float*)d_in[10];
    const float* b_rp  = (const float*)d_in[11];
    const float* W_out = (const float*)d_in[12];
    const float* b_out = (const float*)d_in[13];
    float* out = (float*)d_out;

    float *x, *kraw, *kns, *kne, *gram, *c, *r;
    bf16 *hh, *hl, *W1h, *W1l, *W2h, *W2l, *Wkh, *Wkl, *hidh, *hidl, *hnh, *hnl;
    cudaGetSymbolAddress((void**)&hh,   g_hh);
    cudaGetSymbolAddress((void**)&hl,   g_hl);
    cudaGetSymbolAddress((void**)&W1h,  g_W1h);
    cudaGetSymbolAddress((void**)&W1l,  g_W1l);
    cudaGetSymbolAddress((void**)&W2h,  g_W2h);
    cudaGetSymbolAddress((void**)&W2l,  g_W2l);
    cudaGetSymbolAddress((void**)&Wkh,  g_Wkh);
    cudaGetSymbolAddress((void**)&Wkl,  g_Wkl);
    cudaGetSymbolAddress((void**)&hidh, g_hidh);
    cudaGetSymbolAddress((void**)&hidl, g_hidl);
    cudaGetSymbolAddress((void**)&x,    g_x);
    cudaGetSymbolAddress((void**)&hnh,  g_hnh);
    cudaGetSymbolAddress((void**)&hnl,  g_hnl);
    cudaGetSymbolAddress((void**)&kraw, g_kraw);
    cudaGetSymbolAddress((void**)&kns,  g_kns);
    cudaGetSymbolAddress((void**)&kne,  g_kne);
    cudaGetSymbolAddress((void**)&gram, g_gram);
    cudaGetSymbolAddress((void**)&c,    g_c);
    cudaGetSymbolAddress((void**)&r,    g_r);

    cudaFuncSetAttribute(gemm3_kernel<0>, cudaFuncAttributeMaxDynamicSharedMemorySize, GSMEM);
    cudaFuncSetAttribute(gemm3_kernel<1>, cudaFuncAttributeMaxDynamicSharedMemorySize, GSMEM);
    cudaFuncSetAttribute(gemm3_kernel<2>, cudaFuncAttributeMaxDynamicSharedMemorySize, GSMEM);

    launch_pdl(prep_kernel, dim3(1280 + TOK/4), dim3(256), 0,
               seq, embed, W1, W2, W_sem, W_epi,
               W1h, W1l, W2h, W2l, Wkh, Wkl, hh, hl);
    launch_pdl(gemm3_kernel<1>, dim3(H2_/GBN, TOK/GBM), dim3(256), (size_t)GSMEM,
               (const bf16*)hh, (const bf16*)hl, (const bf16*)W1h, (const bf16*)W1l,
               b1, (const bf16*)nullptr, (const bf16*)nullptr,
               (float*)nullptr, hidh, hidl, TOK, H2_, H_);
    launch_pdl(gemm3_kernel<2>, dim3(H_/GBN, TOK/GBM), dim3(256), (size_t)GSMEM,
               (const bf16*)hidh, (const bf16*)hidl, (const bf16*)W2h, (const bf16*)W2l,
               b2, (const bf16*)hh, (const bf16*)hl,
               x, (bf16*)nullptr, (bf16*)nullptr, TOK, H_, H2_);
    launch_pdl(ln_kernel, dim3(TOK/8), dim3(256), 0,
               (const float*)x, hnh, hnl, gamma, beta);
    launch_pdl(gemm3_kernel<0>, dim3(H_/GBN, TOK/GBM), dim3(256), (size_t)GSMEM,
               (const bf16*)hnh, (const bf16*)hnl, (const bf16*)Wkh, (const bf16*)Wkl,
               (const float*)nullptr, (const bf16*)nullptr, (const bf16*)nullptr,
               kraw, (bf16*)nullptr, (bf16*)nullptr, TOK, H_, H_);
    // W_out L2 prefetch — waits for gemm3<0>, releases dependents immediately,
    // then streams W_out concurrently with knorm/scan/rproj.
    launch_pdl(prefetch_kernel, dim3(512), dim3(256), 0, W_out);
    launch_pdl(knorm_gram_kernel, dim3(512), dim3(256), 0,
               (const float*)kraw, kns, kne, gram);
    launch_pdl(scan_kernel, dim3(256), dim3(256), 0,
               (const float*)kraw, (const float*)kns, (const float*)kne,
               (const float*)gram, c);
    launch_pdl(rproj_kernel, dim3(B_), dim3(H_), 0,
               (const float*)c, W_rp, b_rp, r);
    launch_pdl(out_kernel, dim3(V_/64), dim3(256), 0,
               (const float*)r, W_out, b_out, out);
}

// round 17
// speedup vs baseline: 1.0688x; 1.0415x over previous
#include <cuda_runtime.h>
#include <cuda_bf16.h>
#include <cstdint>

#define B_    16
#define L_    512
#define H_    256
#define V_    32000
#define HALF_ 128
#define TOK   (B_*L_)   // 8192
#define H2_   (2*H_)    // 512
#define NBLK  127       // 4-step scan blocks at t0=4k (127*4=508) + 3 singles = 511

typedef __nv_bfloat16 bf16;
typedef unsigned long long ull;

// ---------------- scratch (device globals) ----------------
__device__ __align__(16) bf16  g_hh [TOK*H_];
__device__ __align__(16) bf16  g_hl [TOK*H_];
__device__ __align__(16) bf16  g_W1h[H2_*H_], g_W1l[H2_*H_];
__device__ __align__(16) bf16  g_W2h[H_*H2_], g_W2l[H_*H2_];
__device__ __align__(16) bf16  g_Wkh[H_*H_],  g_Wkl[H_*H_];
__device__ __align__(16) bf16  g_hidh[TOK*H2_], g_hidl[TOK*H2_];
__device__ __align__(16) float g_x  [TOK*H_];
__device__ __align__(16) bf16  g_hnh[TOK*H_], g_hnl[TOK*H_];
__device__ __align__(16) float g_kraw[TOK*H_];        // [ks | ke] per token, stride 256
__device__ __align__(16) float g_kns[B_*512*HALF_];   // padded to 512 timesteps
__device__ __align__(16) float g_kne[B_*512*HALF_];
__device__ __align__(16) float g_gram[B_*2*NBLK*8];   // {g01,g02,g03,g12,g13,g23,0,0}
__device__ __align__(16) float g_c  [B_*H_];
__device__ __align__(16) float g_r  [B_*H_];

// ---------------- helpers ----------------
__device__ __forceinline__ void gdc_wait() {
    asm volatile("griddepcontrol.wait;" ::: "memory");
}
__device__ __forceinline__ void split2(float v, bf16& hi, bf16& lo) {
    hi = __float2bfloat16(v);
    lo = __float2bfloat16(v - __bfloat162float(hi));
}
__device__ __forceinline__ uint32_t s2u(const void* p) {
    return (uint32_t)__cvta_generic_to_shared(p);
}
__device__ __forceinline__ void cp16(void* s, const void* g) {
    asm volatile("cp.async.cg.shared.global [%0], [%1], 16;\n" :: "r"(s2u(s)), "l"(g));
}
// packed f32x2
__device__ __forceinline__ ull pk2(float a, float b) {
    ull r; asm("mov.b64 %0, {%1, %2};" : "=l"(r) : "f"(a), "f"(b)); return r;
}
__device__ __forceinline__ float2 upk2(ull v) {
    float2 f; asm("mov.b64 {%0, %1}, %2;" : "=f"(f.x), "=f"(f.y) : "l"(v)); return f;
}
__device__ __forceinline__ ull ffma2(ull a, ull b, ull c) {
    ull d; asm("fma.rn.f32x2 %0, %1, %2, %3;" : "=l"(d) : "l"(a), "l"(b), "l"(c)); return d;
}
__device__ __forceinline__ ull fmul2(ull a, ull b) {
    ull d; asm("mul.rn.f32x2 %0, %1, %2;" : "=l"(d) : "l"(a), "l"(b)); return d;
}

// ---------------- merged prep: weight splits + embedding gather ----------------
__global__ void prep_kernel(const int* __restrict__ seq, const float* __restrict__ embed,
                            const float* __restrict__ W1, const float* __restrict__ W2,
                            const float* __restrict__ Wsem, const float* __restrict__ Wepi,
                            bf16* __restrict__ W1h, bf16* __restrict__ W1l,
                            bf16* __restrict__ W2h, bf16* __restrict__ W2l,
                            bf16* __restrict__ Wkh, bf16* __restrict__ Wkl,
                            bf16* __restrict__ hh, bf16* __restrict__ hl) {
    gdc_wait();
    int bx = blockIdx.x, tid = threadIdx.x;
    if (bx < 1280) {
        int i = bx * 256 + tid;
        const float* src; bf16 *hi, *lo; int off;
        if (i < 131072)      { src = W1;   hi = W1h; lo = W1l; off = i; }
        else if (i < 262144) { src = W2;   hi = W2h; lo = W2l; off = i - 131072; }
        else if (i < 294912) { src = Wsem; hi = Wkh; lo = Wkl; off = i - 262144; }
        else                 { src = Wepi; hi = Wkh + 32768; lo = Wkl + 32768; off = i - 294912; }
        bf16 a, b; split2(src[off], a, b);
        hi[off] = a; lo[off] = b;
    } else {
        int tok = (bx - 1280) * 4 + (tid >> 6);
        int col = (tid & 63) * 4;
        int s = __ldg(seq + tok);
        float4 v = *(const float4*)&embed[(size_t)s * H_ + col];
        bf16 h4[4], l4[4];
        split2(v.x, h4[0], l4[0]); split2(v.y, h4[1], l4[1]);
        split2(v.z, h4[2], l4[2]); split2(v.w, h4[3], l4[3]);
        *(uint2*)&hh[(size_t)tok * H_ + col] = *(uint2*)h4;
        *(uint2*)&hl[(size_t)tok * H_ + col] = *(uint2*)l4;
    }
}

// ---------------- bf16x3 split-GEMM, 128x64 tiles, term-major MMA order ----------------
#define GBM 128
#define GBN 64
#define GBK 32
#define SLD (GBK + 8)
#define ATILE (GBM * SLD)
#define BTILE (GBN * SLD)
#define GSMEM ((4*ATILE + 4*BTILE) * 2)   // 61440

#define MMA_BF16(d, a, b) asm volatile( \
    "mma.sync.aligned.m16n8k16.row.col.f32.bf16.bf16.f32 " \
    "{%0,%1,%2,%3},{%4,%5,%6,%7},{%8,%9},{%0,%1,%2,%3};" \
    : "+f"(d[0]), "+f"(d[1]), "+f"(d[2]), "+f"(d[3]) \
    : "r"(a[0]), "r"(a[1]), "r"(a[2]), "r"(a[3]), "r"(b[0]), "r"(b[1]))

#define LDSM4(r0, r1, r2, r3, addr) asm volatile( \
    "ldmatrix.sync.aligned.m8n8.x4.shared.b16 {%0,%1,%2,%3}, [%4];" \
    : "=r"(r0), "=r"(r1), "=r"(r2), "=r"(r3) : "r"(addr))

template<int EPI>
__global__ __launch_bounds__(256, 2)
void gemm3_kernel(const bf16* __restrict__ Ah, const bf16* __restrict__ Al,
                  const bf16* __restrict__ Bh, const bf16* __restrict__ Bl,
                  const float* __restrict__ bias, const bf16* __restrict__ Rh,
                  const bf16* __restrict__ Rl,
                  float* __restrict__ Cf, bf16* __restrict__ Ch, bf16* __restrict__ Cl,
                  int M, int N, int K) {
    extern __shared__ bf16 smem[];
    bf16* As_h = smem;
    bf16* As_l = smem + 2*ATILE;
    bf16* Bs_h = smem + 4*ATILE;
    bf16* Bs_l = smem + 4*ATILE + 2*BTILE;

    const int tid  = threadIdx.x;
    const int wid  = tid >> 5;
    const int lane = tid & 31;
    const int wm   = (wid & 3) * 32;
    const int wn   = (wid >> 2) * 32;
    const int r    = lane >> 2;
    const int q    = lane & 3;
    const int m0   = blockIdx.y * GBM;
    const int n0   = blockIdx.x * GBN;

    const int aoff = (wm + (lane & 15)) * SLD + ((lane >> 4) * 8);
    const int boff = (wn + ((lane >> 4) * 8) + (lane & 7)) * SLD + (((lane >> 3) & 1) * 8);

    float c[2][4][4];
#pragma unroll
    for (int mt = 0; mt < 2; mt++)
#pragma unroll
        for (int nt = 0; nt < 4; nt++)
#pragma unroll
            for (int e = 0; e < 4; e++) c[mt][nt][e] = 0.f;

    auto load_stage = [&](int st, int k0) {
#pragma unroll
        for (int i = tid; i < 512; i += 256) {
            int row = i >> 2, kc = (i & 3) * 8;
            size_t ga = (size_t)(m0 + row) * K + k0 + kc;
            int so = st * ATILE + row * SLD + kc;
            cp16(As_h + so, Ah + ga);
            cp16(As_l + so, Al + ga);
        }
        {
            int i = tid;
            int row = i >> 2, kc = (i & 3) * 8;
            size_t gb = (size_t)(n0 + row) * K + k0 + kc;
            int so = st * BTILE + row * SLD + kc;
            cp16(Bs_h + so, Bh + gb);
            cp16(Bs_l + so, Bl + gb);
        }
        asm volatile("cp.async.commit_group;\n");
    };

    gdc_wait();
    const int T = K / GBK;
    load_stage(0, 0);

    for (int t = 0; t < T; t++) {
        if (t + 1 < T) {
            load_stage((t + 1) & 1, (t + 1) * GBK);
            asm volatile("cp.async.wait_group 1;\n");
        } else {
            asm volatile("cp.async.wait_group 0;\n");
        }
        __syncthreads();

        const uint32_t aBh = s2u(As_h + (t & 1) * ATILE + aoff);
        const uint32_t aBl = s2u(As_l + (t & 1) * ATILE + aoff);
        const uint32_t bBh = s2u(Bs_h + (t & 1) * BTILE + boff);
        const uint32_t bBl = s2u(Bs_l + (t & 1) * BTILE + boff);

#pragma unroll
        for (int kk = 0; kk < GBK; kk += 16) {
            const uint32_t ko = kk * 2;
            uint32_t Afh[2][4], Afl[2][4], Bfh[4][2], Bfl[4][2];
#pragma unroll
            for (int mt = 0; mt < 2; mt++) {
                LDSM4(Afh[mt][0], Afh[mt][1], Afh[mt][2], Afh[mt][3],
                      aBh + (uint32_t)(mt * 16 * SLD * 2) + ko);
                LDSM4(Afl[mt][0], Afl[mt][1], Afl[mt][2], Afl[mt][3],
                      aBl + (uint32_t)(mt * 16 * SLD * 2) + ko);
            }
#pragma unroll
            for (int ntp = 0; ntp < 2; ntp++) {
                LDSM4(Bfh[2*ntp][0], Bfh[2*ntp][1], Bfh[2*ntp+1][0], Bfh[2*ntp+1][1],
                      bBh + (uint32_t)(ntp * 16 * SLD * 2) + ko);
                LDSM4(Bfl[2*ntp][0], Bfl[2*ntp][1], Bfl[2*ntp+1][0], Bfl[2*ntp+1][1],
                      bBl + (uint32_t)(ntp * 16 * SLD * 2) + ko);
            }
#pragma unroll
            for (int mt = 0; mt < 2; mt++)
#pragma unroll
                for (int nt = 0; nt < 4; nt++)
                    MMA_BF16(c[mt][nt], Afh[mt], Bfh[nt]);
#pragma unroll
            for (int mt = 0; mt < 2; mt++)
#pragma unroll
                for (int nt = 0; nt < 4; nt++)
                    MMA_BF16(c[mt][nt], Afh[mt], Bfl[nt]);
#pragma unroll
            for (int mt = 0; mt < 2; mt++)
#pragma unroll
                for (int nt = 0; nt < 4; nt++)
                    MMA_BF16(c[mt][nt], Afl[mt], Bfh[nt]);
        }
        __syncthreads();
    }

#pragma unroll
    for (int mt = 0; mt < 2; mt++)
#pragma unroll
        for (int nt = 0; nt < 4; nt++) {
            int gm = m0 + wm + mt*16 + r;
            int gn = n0 + wn + nt*8 + q*2;
#pragma unroll
            for (int half = 0; half < 2; half++) {
                int m = gm + half*8;
                float v0 = c[mt][nt][half*2 + 0];
                float v1 = c[mt][nt][half*2 + 1];
                size_t o = (size_t)m * N + gn;
                if (EPI == 1) {
                    v0 = fmaxf(v0 + bias[gn],     0.f);
                    v1 = fmaxf(v1 + bias[gn + 1], 0.f);
                    bf16 h0, l0, h1, l1;
                    split2(v0, h0, l0); split2(v1, h1, l1);
                    __nv_bfloat162 ph; ph.x = h0; ph.y = h1;
                    __nv_bfloat162 pl; pl.x = l0; pl.y = l1;
                    *(__nv_bfloat162*)&Ch[o] = ph;
                    *(__nv_bfloat162*)&Cl[o] = pl;
                } else if (EPI == 2) {
                    __nv_bfloat162 rh = *(const __nv_bfloat162*)&Rh[o];
                    __nv_bfloat162 rl = *(const __nv_bfloat162*)&Rl[o];
                    v0 += bias[gn]     + __bfloat162float(rh.x) + __bfloat162float(rl.x);
                    v1 += bias[gn + 1] + __bfloat162float(rh.y) + __bfloat162float(rl.y);
                    float2 p; p.x = v0; p.y = v1;
                    *(float2*)&Cf[o] = p;
                } else {
                    float2 p; p.x = v0; p.y = v1;
                    *(float2*)&Cf[o] = p;
                }
            }
        }
}

// ---------------- LayerNorm: one warp per row, output bf16 split ----------------
__global__ void ln_kernel(const float* __restrict__ x, bf16* __restrict__ hh,
                          bf16* __restrict__ hl, const float* __restrict__ gamma,
                          const float* __restrict__ beta) {
    gdc_wait();
    int row  = blockIdx.x * 8 + (threadIdx.x >> 5);
    int lane = threadIdx.x & 31;
    const float* xr = x + (size_t)row * H_ + lane * 8;
    float4 v0 = *(const float4*)xr;
    float4 v1 = *(const float4*)(xr + 4);
    float s  = v0.x+v0.y+v0.z+v0.w+v1.x+v1.y+v1.z+v1.w;
    float ss = v0.x*v0.x+v0.y*v0.y+v0.z*v0.z+v0.w*v0.w
             + v1.x*v1.x+v1.y*v1.y+v1.z*v1.z+v1.w*v1.w;
#pragma unroll
    for (int o = 16; o; o >>= 1) {
        s  += __shfl_xor_sync(0xffffffffu, s,  o);
        ss += __shfl_xor_sync(0xffffffffu, ss, o);
    }
    float mu  = s * (1.0f / H_);
    float var = ss * (1.0f / H_) - mu * mu;
    float inv = rsqrtf(var + 1e-5f);
    float4 g0 = *(const float4*)(gamma + lane*8);
    float4 g1 = *(const float4*)(gamma + lane*8 + 4);
    float4 b0 = *(const float4*)(beta  + lane*8);
    float4 b1 = *(const float4*)(beta  + lane*8 + 4);
    float y[8] = {
        (v0.x-mu)*inv*g0.x + b0.x, (v0.y-mu)*inv*g0.y + b0.y,
        (v0.z-mu)*inv*g0.z + b0.z, (v0.w-mu)*inv*g0.w + b0.w,
        (v1.x-mu)*inv*g1.x + b1.x, (v1.y-mu)*inv*g1.y + b1.y,
        (v1.z-mu)*inv*g1.z + b1.z, (v1.w-mu)*inv*g1.w + b1.w };
    bf16 oh[8], ol[8];
#pragma unroll
    for (int i = 0; i < 8; i++) split2(y[i], oh[i], ol[i]);
    *(uint4*)&hh[(size_t)row * H_ + lane*8] = *(uint4*)oh;
    *(uint4*)&hl[(size_t)row * H_ + lane*8] = *(uint4*)ol;
}

// ---------------- fused key-normalize + Gram ----------------
__global__ void knorm_gram_kernel(const float* __restrict__ kraw, float* __restrict__ kns,
                                  float* __restrict__ kne, float* __restrict__ gram) {
    gdc_wait();
    int w = blockIdx.x * 8 + (threadIdx.x >> 5);   // 0..4095
    int lane = threadIdx.x & 31;
    int grp = w & 127;            // 4-step group
    int pr  = w >> 7;             // pair 0..31
    int mm = pr & 1, b = pr >> 1;

    float4 v[4];
    float ss[4];
#pragma unroll
    for (int i = 0; i < 4; i++) {
        int t = grp*4 + i;
        if (t < 511) v[i] = *(const float4*)(kraw + ((size_t)(b*L_ + t))*H_ + mm*HALF_ + lane*4);
        else         v[i] = make_float4(0.f, 0.f, 0.f, 0.f);
        ss[i] = v[i].x*v[i].x + v[i].y*v[i].y + v[i].z*v[i].z + v[i].w*v[i].w;
    }
#pragma unroll
    for (int o = 16; o; o >>= 1) {
#pragma unroll
        for (int i = 0; i < 4; i++) ss[i] += __shfl_xor_sync(0xffffffffu, ss[i], o);
    }
    float4 n[4];
    float* dstb = (mm ? kne : kns) + (size_t)b*512*HALF_;
#pragma unroll
    for (int i = 0; i < 4; i++) {
        float inv = 1.0f / fmaxf(sqrtf(ss[i]), 1e-12f);
        n[i].x = v[i].x*inv; n[i].y = v[i].y*inv; n[i].z = v[i].z*inv; n[i].w = v[i].w*inv;
        int t = grp*4 + i;
        if (t < 511) *(float4*)(dstb + (size_t)t*HALF_ + lane*4) = n[i];
    }
    if (grp >= NBLK) return;
    float d01 = n[0].x*n[1].x + n[0].y*n[1].y + n[0].z*n[1].z + n[0].w*n[1].w;
    float d02 = n[0].x*n[2].x + n[0].y*n[2].y + n[0].z*n[2].z + n[0].w*n[2].w;
    float d03 = n[0].x*n[3].x + n[0].y*n[3].y + n[0].z*n[3].z + n[0].w*n[3].w;
    float d12 = n[1].x*n[2].x + n[1].y*n[2].y + n[1].z*n[2].z + n[1].w*n[2].w;
    float d13 = n[1].x*n[3].x + n[1].y*n[3].y + n[1].z*n[3].z + n[1].w*n[3].w;
    float d23 = n[2].x*n[3].x + n[2].y*n[3].y + n[2].z*n[3].z + n[2].w*n[3].w;
#pragma unroll
    for (int o = 16; o; o >>= 1) {
        d01 += __shfl_xor_sync(0xffffffffu, d01, o);
        d02 += __shfl_xor_sync(0xffffffffu, d02, o);
        d03 += __shfl_xor_sync(0xffffffffu, d03, o);
        d12 += __shfl_xor_sync(0xffffffffu, d12, o);
        d13 += __shfl_xor_sync(0xffffffffu, d13, o);
        d23 += __shfl_xor_sync(0xffffffffu, d23, o);
    }
    if (lane == 0) {
        float* gp = gram + (size_t)(pr*NBLK + grp) * 8;
        float4 a; a.x = d01; a.y = d02; a.z = d03; a.w = d12;
        float4 bb; bb.x = d13; bb.y = d23; bb.z = 0.f; bb.w = 0.f;
        *(float4*)gp = a;
        *(float4*)(gp + 4) = bb;
    }
}

// ---------------- blocked delta-rule scan: SMEM-staged, 2 rows/warp ----------------
// Also L2-prefetches W_out (fire-and-forget) during the scan to warm out_kernel's reads.
__global__ __launch_bounds__(256)
void scan_kernel(const float* __restrict__ kraw,
                 const float* __restrict__ kns, const float* __restrict__ kne,
                 const float* __restrict__ gram, float* __restrict__ co,
                 const float* __restrict__ W_out) {
    __shared__ float ksm[2][32*HALF_];   // 2 x 16KB

    const int bx = blockIdx.x;
    const int rg = bx & 7;
    const int pr = bx >> 3;              // pair 0..31
    const int mm = pr & 1, b = pr >> 1;
    const int w = threadIdx.x >> 5, lane = threadIdx.x & 31;
    const int r0 = rg*16 + w*2;          // rows r0, r0+1

    const float* kn = (mm ? kne : kns) + (size_t)b*512*HALF_;
    const float* kr = kraw + (size_t)b*L_*H_ + mm*HALF_;
    const float* gr = gram + (size_t)pr*NBLK*8;
    // this block's W_out prefetch slice: 1000 lines of 128B (256 blocks cover 32.8MB)
    const char* wpf = (const char*)W_out + (size_t)bx * 1000 * 128;

    auto issue = [&](int cc) {
        const float* src = kn + (size_t)cc*32*HALF_;
        float* dst = ksm[cc & 1];
#pragma unroll
        for (int j = 0; j < 4; j++) {
            int pos = threadIdx.x + j*256;
            cp16(dst + pos*4, src + pos*4);
        }
        asm volatile("cp.async.commit_group;\n");
    };

    ull s0a = 0, s0b = 0, s1a = 0, s1b = 0;

    gdc_wait();
    issue(0); issue(1);

    for (int c = 0; c < 16; c++) {
        if (c == 15) asm volatile("cp.async.wait_group 0;\n");
        else         asm volatile("cp.async.wait_group 1;\n");
        __syncthreads();
        // W_out L2 prefetch: 64 lines per iteration (threads 0..63), no register dep
        {
            int li = c*64 + (int)threadIdx.x;
            if (threadIdx.x < 64 && li < 1000) {
                asm volatile("prefetch.global.L2 [%0];" :: "l"(wpf + (size_t)li * 128));
            }
        }
        const float* buf = ksm[c & 1];
        const int nb = (c == 15) ? 7 : 8;
        for (int j = 0; j < nb; j++) {
            const int blk = c*8 + j;
            const int ts = j*4;
            ull na[4], nb2[4];
#pragma unroll
            for (int i = 0; i < 4; i++) {
                float4 n4 = *(const float4*)(buf + (ts+i)*HALF_ + lane*4);
                na[i] = pk2(n4.x, n4.y); nb2[i] = pk2(n4.z, n4.w);
            }
            float4 gv0 = *(const float4*)(gr + blk*8);
            float4 gv1 = *(const float4*)(gr + blk*8 + 4);
            const float* kb = kr + (size_t)(blk*4)*H_ + r0;
            float k00 = __ldg(kb),         k01 = __ldg(kb + H_);
            float k02 = __ldg(kb + 2*H_),  k03 = __ldg(kb + 3*H_);
            float k10 = __ldg(kb + 1),     k11 = __ldg(kb + H_ + 1);
            float k12 = __ldg(kb + 2*H_+1),k13 = __ldg(kb + 3*H_ + 1);

            float v[8];
#pragma unroll
            for (int i = 0; i < 4; i++) {
                float2 ta = upk2(ffma2(s0b, nb2[i], fmul2(s0a, na[i])));
                v[i]   = ta.x + ta.y;
                float2 tb = upk2(ffma2(s1b, nb2[i], fmul2(s1a, na[i])));
                v[4+i] = tb.x + tb.y;
            }
            float u0[4];
#pragma unroll
            for (int jj = 0; jj < 4; jj++) {
                float lo = v[jj], hi = v[jj+4];
                float mine = (lane & 16) ? hi : lo;
                float oth  = (lane & 16) ? lo : hi;
                u0[jj] = mine + __shfl_xor_sync(0xffffffffu, oth, 16);
            }
            float w0[2];
#pragma unroll
            for (int jj = 0; jj < 2; jj++) {
                float mine = (lane & 8) ? u0[jj+2] : u0[jj];
                float oth  = (lane & 8) ? u0[jj]   : u0[jj+2];
                w0[jj] = mine + __shfl_xor_sync(0xffffffffu, oth, 8);
            }
            {
                float mine = (lane & 4) ? w0[1] : w0[0];
                float oth  = (lane & 4) ? w0[0] : w0[1];
                float z = mine + __shfl_xor_sync(0xffffffffu, oth, 4);
                z += __shfl_xor_sync(0xffffffffu, z, 2);
                z += __shfl_xor_sync(0xffffffffu, z, 1);
                float p00 = __shfl_sync(0xffffffffu, z, 0);
                float p01 = __shfl_sync(0xffffffffu, z, 4);
                float p02 = __shfl_sync(0xffffffffu, z, 8);
                float p03 = __shfl_sync(0xffffffffu, z, 12);
                float p10 = __shfl_sync(0xffffffffu, z, 16);
                float p11 = __shfl_sync(0xffffffffu, z, 20);
                float p12 = __shfl_sync(0xffffffffu, z, 24);
                float p13 = __shfl_sync(0xffffffffu, z, 28);
                float d00 = k00 - p00;
                float d01 = k01 - p01 - d00*gv0.x;
                float d02 = k02 - p02 - d00*gv0.y - d01*gv0.w;
                float d03 = k03 - p03 - d00*gv0.z - d01*gv1.x - d02*gv1.y;
                float d10 = k10 - p10;
                float d11 = k11 - p11 - d10*gv0.x;
                float d12v= k12 - p12 - d10*gv0.y - d11*gv0.w;
                float d13v= k13 - p13 - d10*gv0.z - d11*gv1.x - d12v*gv1.y;
                ull D;
                D = pk2(d00, d00); s0a = ffma2(D, na[0], s0a); s0b = ffma2(D, nb2[0], s0b);
                D = pk2(d01, d01); s0a = ffma2(D, na[1], s0a); s0b = ffma2(D, nb2[1], s0b);
                D = pk2(d02, d02); s0a = ffma2(D, na[2], s0a); s0b = ffma2(D, nb2[2], s0b);
                D = pk2(d03, d03); s0a = ffma2(D, na[3], s0a); s0b = ffma2(D, nb2[3], s0b);
                D = pk2(d10, d10); s1a = ffma2(D, na[0], s1a); s1b = ffma2(D, nb2[0], s1b);
                D = pk2(d11, d11); s1a = ffma2(D, na[1], s1a); s1b = ffma2(D, nb2[1], s1b);
                D = pk2(d12v,d12v);s1a = ffma2(D, na[2], s1a); s1b = ffma2(D, nb2[2], s1b);
                D = pk2(d13v,d13v);s1a = ffma2(D, na[3], s1a); s1b = ffma2(D, nb2[3], s1b);
            }
        }
        __syncthreads();
        if (c + 2 < 16) issue(c + 2);
    }

    // singles t = 508..510 (chunk 15 buffer = ksm[1])
    {
        const float* buf = ksm[1];
        for (int t = 508; t <= 510; t++) {
            float4 n4 = *(const float4*)(buf + (t-480)*HALF_ + lane*4);
            ull na = pk2(n4.x, n4.y), nb2 = pk2(n4.z, n4.w);
            float2 ta = upk2(ffma2(s0b, nb2, fmul2(s0a, na)));
            float p0 = ta.x + ta.y;
            float2 tb = upk2(ffma2(s1b, nb2, fmul2(s1a, na)));
            float p1 = tb.x + tb.y;
#pragma unroll
            for (int o = 16; o; o >>= 1) {
                p0 += __shfl_xor_sync(0xffffffffu, p0, o);
                p1 += __shfl_xor_sync(0xffffffffu, p1, o);
            }
            float k0v = __ldg(kr + (size_t)t*H_ + r0);
            float k1v = __ldg(kr + (size_t)t*H_ + r0 + 1);
            ull D0 = pk2(k0v - p0, k0v - p0);
            ull D1 = pk2(k1v - p1, k1v - p1);
            s0a = ffma2(D0, na, s0a); s0b = ffma2(D0, nb2, s0b);
            s1a = ffma2(D1, na, s1a); s1b = ffma2(D1, nb2, s1b);
        }
    }

    // final read with raw last-token key (t = 511)
    {
        float4 q4 = *(const float4*)(kr + (size_t)511*H_ + lane*4);
        ull qa = pk2(q4.x, q4.y), qb = pk2(q4.z, q4.w);
        float2 ta = upk2(ffma2(s0b, qb, fmul2(s0a, qa)));
        float p0 = ta.x + ta.y;
        float2 tb = upk2(ffma2(s1b, qb, fmul2(s1a, qa)));
        float p1 = tb.x + tb.y;
#pragma unroll
        for (int o = 16; o; o >>= 1) {
            p0 += __shfl_xor_sync(0xffffffffu, p0, o);
            p1 += __shfl_xor_sync(0xffffffffu, p1, o);
        }
        if (lane == 0) {
            co[b*H_ + mm*HALF_ + r0]     = p0;
            co[b*H_ + mm*HALF_ + r0 + 1] = p1;
        }
    }
}

// ---------------- r = c @ W_rp^T + b_rp ----------------
__global__ void rproj_kernel(const float* __restrict__ c, const float* __restrict__ W_rp,
                             const float* __restrict__ b_rp, float* __restrict__ r) {
    gdc_wait();
    int b = blockIdx.x;
    int j = threadIdx.x;
    __shared__ float cs[H_];
    cs[j] = c[b*H_ + j];
    __syncthreads();
    float acc = b_rp[j];
    const float* w = W_rp + (size_t)j*H_;
#pragma unroll 8
    for (int k = 0; k < H_; k++) acc += w[k] * cs[k];
    r[b*H_ + j] = acc;
}

// ---------------- out = r @ W_out^T + b_out: VB=64, cp.async double-buffered W ----------------
__global__ __launch_bounds__(256)
void out_kernel(const float* __restrict__ r, const float* __restrict__ W_out,
                const float* __restrict__ b_out, float* __restrict__ out) {
    const int VB = 64, KC = 32;
    __shared__ float rs[B_*H_];                  // 16 KB
    __shared__ float ws[2][VB][KC + 4];
    int tid = threadIdx.x;
    int vl  = tid & 63;
    int bh  = tid >> 6;                          // batch quarter: 0..3
    int v   = blockIdx.x * VB + vl;

    auto wload = [&](int st, int kc) {
#pragma unroll
        for (int u = 0; u < 2; u++) {
            int unit = tid + u*256;
            int row = unit >> 3, c4 = (unit & 7) * 4;
            cp16(&ws[st][row][c4],
                 &W_out[(size_t)(blockIdx.x*VB + row)*H_ + kc + c4]);
        }
        asm volatile("cp.async.commit_group;\n");
    };

    gdc_wait();
    for (int e = tid*4; e < B_*H_; e += 1024) *(float4*)&rs[e] = *(const float4*)&r[e];
    wload(0, 0);

    float acc[4] = {0.f, 0.f, 0.f, 0.f};
    const int NC = H_ / KC;                      // 8 chunks
    for (int cchunk = 0; cchunk < NC; cchunk++) {
        if (cchunk + 1 < NC) {
            wload((cchunk + 1) & 1, (cchunk + 1) * KC);
            asm volatile("cp.async.wait_group 1;\n");
        } else {
            asm volatile("cp.async.wait_group 0;\n");
        }
        __syncthreads();
        const int kc = cchunk * KC;
        const int st = cchunk & 1;
#pragma unroll
        for (int k = 0; k < KC; k += 4) {
            float4 w4 = *(const float4*)&ws[st][vl][k];
#pragma unroll
            for (int b = 0; b < 4; b++) {
                float4 r4 = *(const float4*)&rs[(bh*4 + b)*H_ + kc + k];
                acc[b] += w4.x*r4.x + w4.y*r4.y + w4.z*r4.z + w4.w*r4.w;
            }
        }
        __syncthreads();
    }
    float bo = b_out[v];
#pragma unroll
    for (int b = 0; b < 4; b++) out[(size_t)(bh*4 + b)*V_ + v] = acc[b] + bo;
}

// ---------------- PDL launch helper ----------------
template<typename F, typename... Args>
static inline void launch_pdl(F func, dim3 grid, dim3 block, size_t smem, Args... args) {
    cudaLaunchAttribute attr[1];
    attr[0].id = cudaLaunchAttributeProgrammaticStreamSerialization;
    attr[0].val.programmaticStreamSerializationAllowed = 1;
    cudaLaunchConfig_t cfg = {};
    cfg.gridDim = grid;
    cfg.blockDim = block;
    cfg.dynamicSmemBytes = smem;
    cfg.stream = 0;
    cfg.attrs = attr;
    cfg.numAttrs = 1;
    cudaLaunchKernelEx(&cfg, func, args...);
}

// ---------------- launch ----------------
extern "C" void kernel_launch(void* const* d_in, const int* in_sizes, int n_in,
                              void* d_out, int out_size) {
    const int*   seq   = (const int*)  d_in[0];
    const float* embed = (const float*)d_in[1];
    const float* W1    = (const float*)d_in[2];
    const float* b1    = (const float*)d_in[3];
    const float* W2    = (const float*)d_in[4];
    const float* b2    = (const float*)d_in[5];
    const float* gamma = (const float*)d_in[6];
    const float* beta  = (const float*)d_in[7];
    const float* W_sem = (const float*)d_in[8];
    const float* W_epi = (const float*)d_in[9];
    const float* W_rp  = (const float*)d_in[10];
    const float* b_rp  = (const float*)d_in[11];
    const float* W_out = (const float*)d_in[12];
    const float* b_out = (const float*)d_in[13];
    float* out = (float*)d_out;

    float *x, *kraw, *kns, *kne, *gram, *c, *r;
    bf16 *hh, *hl, *W1h, *W1l, *W2h, *W2l, *Wkh, *Wkl, *hidh, *hidl, *hnh, *hnl;
    cudaGetSymbolAddress((void**)&hh,   g_hh);
    cudaGetSymbolAddress((void**)&hl,   g_hl);
    cudaGetSymbolAddress((void**)&W1h,  g_W1h);
    cudaGetSymbolAddress((void**)&W1l,  g_W1l);
    cudaGetSymbolAddress((void**)&W2h,  g_W2h);
    cudaGetSymbolAddress((void**)&W2l,  g_W2l);
    cudaGetSymbolAddress((void**)&Wkh,  g_Wkh);
    cudaGetSymbolAddress((void**)&Wkl,  g_Wkl);
    cudaGetSymbolAddress((void**)&hidh, g_hidh);
    cudaGetSymbolAddress((void**)&hidl, g_hidl);
    cudaGetSymbolAddress((void**)&x,    g_x);
    cudaGetSymbolAddress((void**)&hnh,  g_hnh);
    cudaGetSymbolAddress((void**)&hnl,  g_hnl);
    cudaGetSymbolAddress((void**)&kraw, g_kraw);
    cudaGetSymbolAddress((void**)&kns,  g_kns);
    cudaGetSymbolAddress((void**)&kne,  g_kne);
    cudaGetSymbolAddress((void**)&gram, g_gram);
    cudaGetSymbolAddress((void**)&c,    g_c);
    cudaGetSymbolAddress((void**)&r,    g_r);

    cudaFuncSetAttribute(gemm3_kernel<0>, cudaFuncAttributeMaxDynamicSharedMemorySize, GSMEM);
    cudaFuncSetAttribute(gemm3_kernel<1>, cudaFuncAttributeMaxDynamicSharedMemorySize, GSMEM);
    cudaFuncSetAttribute(gemm3_kernel<2>, cudaFuncAttributeMaxDynamicSharedMemorySize, GSMEM);

    launch_pdl(prep_kernel, dim3(1280 + TOK/4), dim3(256), 0,
               seq, embed, W1, W2, W_sem, W_epi,
               W1h, W1l, W2h, W2l, Wkh, Wkl, hh, hl);
    launch_pdl(gemm3_kernel<1>, dim3(H2_/GBN, TOK/GBM), dim3(256), (size_t)GSMEM,
               (const bf16*)hh, (const bf16*)hl, (const bf16*)W1h, (const bf16*)W1l,
               b1, (const bf16*)nullptr, (const bf16*)nullptr,
               (float*)nullptr, hidh, hidl, TOK, H2_, H_);
    launch_pdl(gemm3_kernel<2>, dim3(H_/GBN, TOK/GBM), dim3(256), (size_t)GSMEM,
               (const bf16*)hidh, (const bf16*)hidl, (const bf16*)W2h, (const bf16*)W2l,
               b2, (const bf16*)hh, (const bf16*)hl,
               x, (bf16*)nullptr, (bf16*)nullptr, TOK, H_, H2_);
    launch_pdl(ln_kernel, dim3(TOK/8), dim3(256), 0,
               (const float*)x, hnh, hnl, gamma, beta);
    launch_pdl(gemm3_kernel<0>, dim3(H_/GBN, TOK/GBM), dim3(256), (size_t)GSMEM,
               (const bf16*)hnh, (const bf16*)hnl, (const bf16*)Wkh, (const bf16*)Wkl,
               (const float*)nullptr, (const bf16*)nullptr, (const bf16*)nullptr,
               kraw, (bf16*)nullptr, (bf16*)nullptr, TOK, H_, H_);
    launch_pdl(knorm_gram_kernel, dim3(512), dim3(256), 0,
               (const float*)kraw, kns, kne, gram);
    launch_pdl(scan_kernel, dim3(256), dim3(256), 0,
               (const float*)kraw, (const float*)kns, (const float*)kne,
               (const float*)gram, c, W_out);
    launch_pdl(rproj_kernel, dim3(B_), dim3(H_), 0,
               (const float*)c, W_rp, b_rp, r);
    launch_pdl(out_kernel, dim3(V_/64), dim3(256), 0,
               (const float*)r, W_out, b_out, out);
}